// round 1
// baseline (speedup 1.0000x reference)
#include <cuda_runtime.h>
#include <math.h>

#define S_LEN  2048
#define DMODEL 1024
#define NHEADS 16
#define DK     64
#define BATCH  2
#define MROWS  (BATCH * S_LEN)   // 4096

// Scratch (device globals; no allocation allowed)
__device__ float g_Q[BATCH * NHEADS * S_LEN * DK];  // (b,h,s,d) 16MB
__device__ float g_K[BATCH * NHEADS * S_LEN * DK];
__device__ float g_V[BATCH * NHEADS * S_LEN * DK];
__device__ float g_O[MROWS * DMODEL];               // (b*s, D)   16MB

// ---------------------------------------------------------------------------
// Fused QKV GEMM:  out = x @ W^T  (W is (N,K) row-major, dot of rows)
// blockIdx.z selects {Wq,Wk,Wv}. Epilogue applies RoPE (z<2) and writes
// directly into (b,h,s,d) layout.
// Tile: 64x64, BK=16, 256 threads, 4x4 per-thread microtile.
// ---------------------------------------------------------------------------
__global__ __launch_bounds__(256) void gemm_qkv_kernel(
    const float* __restrict__ x,
    const float* __restrict__ Wq,
    const float* __restrict__ Wk,
    const float* __restrict__ Wv,
    const int*   __restrict__ pos)
{
    const int z = blockIdx.z;
    const float* __restrict__ W = (z == 0) ? Wq : ((z == 1) ? Wk : Wv);
    float* __restrict__ outp    = (z == 0) ? g_Q : ((z == 1) ? g_K : g_V);

    __shared__ float As[16 * 64];
    __shared__ float Bs[16 * 64];

    const int t  = threadIdx.x;
    const int tx = t & 15;        // 0..15 -> output cols tx*4..tx*4+3
    const int ty = t >> 4;        // 0..15 -> output rows ty*4..ty*4+3
    const int n0 = blockIdx.x * 64;
    const int m0 = blockIdx.y * 64;

    const int ar = t >> 2;            // 0..63 row within tile
    const int ak = (t & 3) << 2;      // 0,4,8,12 k-offset

    float acc[4][4];
#pragma unroll
    for (int i = 0; i < 4; i++)
#pragma unroll
        for (int j = 0; j < 4; j++) acc[i][j] = 0.f;

    for (int k0 = 0; k0 < DMODEL; k0 += 16) {
        float4 av = *(const float4*)(x + (size_t)(m0 + ar) * DMODEL + k0 + ak);
        float4 bv = *(const float4*)(W + (size_t)(n0 + ar) * DMODEL + k0 + ak);
        As[(ak + 0) * 64 + ar] = av.x;
        As[(ak + 1) * 64 + ar] = av.y;
        As[(ak + 2) * 64 + ar] = av.z;
        As[(ak + 3) * 64 + ar] = av.w;
        Bs[(ak + 0) * 64 + ar] = bv.x;
        Bs[(ak + 1) * 64 + ar] = bv.y;
        Bs[(ak + 2) * 64 + ar] = bv.z;
        Bs[(ak + 3) * 64 + ar] = bv.w;
        __syncthreads();
#pragma unroll
        for (int kk = 0; kk < 16; kk++) {
            float4 a = *(const float4*)(As + kk * 64 + ty * 4);
            float4 b = *(const float4*)(Bs + kk * 64 + tx * 4);
            float af[4] = {a.x, a.y, a.z, a.w};
            float bf[4] = {b.x, b.y, b.z, b.w};
#pragma unroll
            for (int i = 0; i < 4; i++)
#pragma unroll
                for (int j = 0; j < 4; j++) acc[i][j] += af[i] * bf[j];
        }
        __syncthreads();
    }

    // Epilogue: write (b,h,s,d) layout; RoPE for Q,K
    const int h  = n0 >> 6;       // tile spans exactly one head
    const int c0 = tx * 4;        // column within head, even

    if (z == 2) {
#pragma unroll
        for (int i = 0; i < 4; i++) {
            int m = m0 + ty * 4 + i;
            int b = m >> 11, srow = m & (S_LEN - 1);
            *(float4*)(outp + (((size_t)(b * NHEADS + h) * S_LEN + srow) * DK) + c0) =
                make_float4(acc[i][0], acc[i][1], acc[i][2], acc[i][3]);
        }
    } else {
        // inv_freq = theta^(-(2j)/64); pair0 uses 2j=c0, pair1 uses 2j=c0+2
        const float neg_ln_theta_over_dk = -logf(10000.0f) / 64.0f;
        const float f0 = expf((float)(c0)     * neg_ln_theta_over_dk);
        const float f1 = expf((float)(c0 + 2) * neg_ln_theta_over_dk);
#pragma unroll
        for (int i = 0; i < 4; i++) {
            int m = m0 + ty * 4 + i;
            int b = m >> 11, srow = m & (S_LEN - 1);
            float p = (float)pos[srow];
            float s0, cv0, s1, cv1;
            sincosf(p * f0, &s0, &cv0);
            sincosf(p * f1, &s1, &cv1);
            float r0 = acc[i][0] * cv0 - acc[i][1] * s0;
            float r1 = acc[i][0] * s0  + acc[i][1] * cv0;
            float r2 = acc[i][2] * cv1 - acc[i][3] * s1;
            float r3 = acc[i][2] * s1  + acc[i][3] * cv1;
            *(float4*)(outp + (((size_t)(b * NHEADS + h) * S_LEN + srow) * DK) + c0) =
                make_float4(r0, r1, r2, r3);
        }
    }
}

// ---------------------------------------------------------------------------
// Flash attention (causal). One CTA = 64 query rows for one (b,h).
// 256 threads (16x16), 4x4 per-thread fragments, online softmax.
// Smem: Q (transposed), K (transposed, reused as P), V (natural).
// ---------------------------------------------------------------------------
__global__ __launch_bounds__(256) void attn_kernel()
{
    __shared__ float Qs [64 * 64];
    __shared__ float KPs[64 * 64];
    __shared__ float Vs [64 * 64];

    const int t  = threadIdx.x;
    const int tx = t & 15;
    const int ty = t >> 4;
    const int q0 = blockIdx.x * 64;
    const int h  = blockIdx.y;
    const int b  = blockIdx.z;
    const int bh = b * NHEADS + h;

    const float* __restrict__ Qp = g_Q + (size_t)bh * S_LEN * DK;
    const float* __restrict__ Kp = g_K + (size_t)bh * S_LEN * DK;
    const float* __restrict__ Vp = g_V + (size_t)bh * S_LEN * DK;

    // Load Q tile transposed: Qs[d][r]
#pragma unroll
    for (int idx = t; idx < 1024; idx += 256) {
        int row = idx >> 4, d4 = (idx & 15) << 2;
        float4 v = *(const float4*)(Qp + (size_t)(q0 + row) * DK + d4);
        Qs[(d4 + 0) * 64 + row] = v.x;
        Qs[(d4 + 1) * 64 + row] = v.y;
        Qs[(d4 + 2) * 64 + row] = v.z;
        Qs[(d4 + 3) * 64 + row] = v.w;
    }

    float acc[4][4];
    float m[4], l[4];
#pragma unroll
    for (int i = 0; i < 4; i++) {
        m[i] = -1e30f;
        l[i] = 0.f;
#pragma unroll
        for (int j = 0; j < 4; j++) acc[i][j] = 0.f;
    }

    const int ntiles = (q0 >> 6) + 1;
    for (int kt = 0; kt < ntiles; kt++) {
        const int k0 = kt * 64;
        __syncthreads();  // prev PV reads done; also fences Q load on first iter path below

        // Load K transposed into KPs, V natural into Vs
#pragma unroll
        for (int idx = t; idx < 1024; idx += 256) {
            int row = idx >> 4, d4 = (idx & 15) << 2;
            float4 kv = *(const float4*)(Kp + (size_t)(k0 + row) * DK + d4);
            KPs[(d4 + 0) * 64 + row] = kv.x;
            KPs[(d4 + 1) * 64 + row] = kv.y;
            KPs[(d4 + 2) * 64 + row] = kv.z;
            KPs[(d4 + 3) * 64 + row] = kv.w;
            float4 vv = *(const float4*)(Vp + (size_t)(k0 + row) * DK + d4);
            *(float4*)(Vs + row * 64 + d4) = vv;
        }
        __syncthreads();

        // S = Q K^T fragment
        float sreg[4][4];
#pragma unroll
        for (int i = 0; i < 4; i++)
#pragma unroll
            for (int j = 0; j < 4; j++) sreg[i][j] = 0.f;

#pragma unroll
        for (int kk = 0; kk < 64; kk++) {
            float4 qv = *(const float4*)(Qs  + kk * 64 + ty * 4);
            float4 kv = *(const float4*)(KPs + kk * 64 + tx * 4);
            float qf[4] = {qv.x, qv.y, qv.z, qv.w};
            float kf[4] = {kv.x, kv.y, kv.z, kv.w};
#pragma unroll
            for (int i = 0; i < 4; i++)
#pragma unroll
                for (int j = 0; j < 4; j++) sreg[i][j] += qf[i] * kf[j];
        }

        // Scale + causal mask (only diagonal tile needs masking)
        const bool diag = (k0 == q0);
#pragma unroll
        for (int i = 0; i < 4; i++)
#pragma unroll
            for (int j = 0; j < 4; j++) {
                float v = sreg[i][j] * 0.125f;   // 1/sqrt(64)
                if (diag && (tx * 4 + j) > (ty * 4 + i)) v = -1e30f;
                sreg[i][j] = v;
            }

        // Online softmax update (row reductions over the 16 tx lanes)
#pragma unroll
        for (int i = 0; i < 4; i++) {
            float mloc = fmaxf(fmaxf(sreg[i][0], sreg[i][1]),
                               fmaxf(sreg[i][2], sreg[i][3]));
            mloc = fmaxf(mloc, __shfl_xor_sync(0xffffffffu, mloc, 1));
            mloc = fmaxf(mloc, __shfl_xor_sync(0xffffffffu, mloc, 2));
            mloc = fmaxf(mloc, __shfl_xor_sync(0xffffffffu, mloc, 4));
            mloc = fmaxf(mloc, __shfl_xor_sync(0xffffffffu, mloc, 8));
            float mn = fmaxf(m[i], mloc);
            float al = __expf(m[i] - mn);
            m[i] = mn;
            float ls = 0.f;
#pragma unroll
            for (int j = 0; j < 4; j++) {
                sreg[i][j] = __expf(sreg[i][j] - mn);
                ls += sreg[i][j];
            }
            ls += __shfl_xor_sync(0xffffffffu, ls, 1);
            ls += __shfl_xor_sync(0xffffffffu, ls, 2);
            ls += __shfl_xor_sync(0xffffffffu, ls, 4);
            ls += __shfl_xor_sync(0xffffffffu, ls, 8);
            l[i] = l[i] * al + ls;
#pragma unroll
            for (int j = 0; j < 4; j++) acc[i][j] *= al;
        }

        __syncthreads();  // all K reads complete before P overwrites KPs
#pragma unroll
        for (int i = 0; i < 4; i++)
            *(float4*)(KPs + (ty * 4 + i) * 64 + tx * 4) =
                make_float4(sreg[i][0], sreg[i][1], sreg[i][2], sreg[i][3]);
        __syncthreads();

        // O += P V
#pragma unroll
        for (int jj = 0; jj < 64; jj++) {
            float4 vv = *(const float4*)(Vs + jj * 64 + tx * 4);
#pragma unroll
            for (int i = 0; i < 4; i++) {
                float p = KPs[(ty * 4 + i) * 64 + jj];
                acc[i][0] += p * vv.x;
                acc[i][1] += p * vv.y;
                acc[i][2] += p * vv.z;
                acc[i][3] += p * vv.w;
            }
        }
    }

    // Normalize and write into (b*s, D) layout for the output projection
#pragma unroll
    for (int i = 0; i < 4; i++) {
        float inv = 1.0f / l[i];
        int srow = q0 + ty * 4 + i;
        *(float4*)(g_O + (size_t)(b * S_LEN + srow) * DMODEL + h * DK + tx * 4) =
            make_float4(acc[i][0] * inv, acc[i][1] * inv,
                        acc[i][2] * inv, acc[i][3] * inv);
    }
}

// ---------------------------------------------------------------------------
// Output projection: out = g_O @ Wo^T  (plain GEMM, same tiling)
// ---------------------------------------------------------------------------
__global__ __launch_bounds__(256) void gemm_o_kernel(
    const float* __restrict__ Wo, float* __restrict__ out)
{
    __shared__ float As[16 * 64];
    __shared__ float Bs[16 * 64];

    const int t  = threadIdx.x;
    const int tx = t & 15;
    const int ty = t >> 4;
    const int n0 = blockIdx.x * 64;
    const int m0 = blockIdx.y * 64;
    const int ar = t >> 2;
    const int ak = (t & 3) << 2;

    float acc[4][4];
#pragma unroll
    for (int i = 0; i < 4; i++)
#pragma unroll
        for (int j = 0; j < 4; j++) acc[i][j] = 0.f;

    for (int k0 = 0; k0 < DMODEL; k0 += 16) {
        float4 av = *(const float4*)(g_O + (size_t)(m0 + ar) * DMODEL + k0 + ak);
        float4 bv = *(const float4*)(Wo  + (size_t)(n0 + ar) * DMODEL + k0 + ak);
        As[(ak + 0) * 64 + ar] = av.x;
        As[(ak + 1) * 64 + ar] = av.y;
        As[(ak + 2) * 64 + ar] = av.z;
        As[(ak + 3) * 64 + ar] = av.w;
        Bs[(ak + 0) * 64 + ar] = bv.x;
        Bs[(ak + 1) * 64 + ar] = bv.y;
        Bs[(ak + 2) * 64 + ar] = bv.z;
        Bs[(ak + 3) * 64 + ar] = bv.w;
        __syncthreads();
#pragma unroll
        for (int kk = 0; kk < 16; kk++) {
            float4 a = *(const float4*)(As + kk * 64 + ty * 4);
            float4 b = *(const float4*)(Bs + kk * 64 + tx * 4);
            float af[4] = {a.x, a.y, a.z, a.w};
            float bf[4] = {b.x, b.y, b.z, b.w};
#pragma unroll
            for (int i = 0; i < 4; i++)
#pragma unroll
                for (int j = 0; j < 4; j++) acc[i][j] += af[i] * bf[j];
        }
        __syncthreads();
    }

#pragma unroll
    for (int i = 0; i < 4; i++) {
        *(float4*)(out + (size_t)(m0 + ty * 4 + i) * DMODEL + n0 + tx * 4) =
            make_float4(acc[i][0], acc[i][1], acc[i][2], acc[i][3]);
    }
}

// ---------------------------------------------------------------------------
extern "C" void kernel_launch(void* const* d_in, const int* in_sizes, int n_in,
                              void* d_out, int out_size)
{
    const float* x   = (const float*)d_in[0];
    const int*   pos = (const int*)  d_in[1];
    const float* Wq  = (const float*)d_in[2];
    const float* Wk  = (const float*)d_in[3];
    const float* Wv  = (const float*)d_in[4];
    const float* Wo  = (const float*)d_in[5];
    float* out = (float*)d_out;

    dim3 blk(256);
    // QKV projections + RoPE (z selects matrix)
    gemm_qkv_kernel<<<dim3(DMODEL / 64, MROWS / 64, 3), blk>>>(x, Wq, Wk, Wv, pos);
    // Causal flash attention
    attn_kernel<<<dim3(S_LEN / 64, NHEADS, BATCH), blk>>>();
    // Output projection
    gemm_o_kernel<<<dim3(DMODEL / 64, MROWS / 64, 1), blk>>>(Wo, out);
}

// round 4
// speedup vs baseline: 1.3355x; 1.3355x over previous
#include <cuda_runtime.h>
#include <math.h>
#include <stdint.h>

#define S_LEN  2048
#define DMODEL 1024
#define NHEADS 16
#define DK     64
#define BATCH  2
#define MROWS  (BATCH * S_LEN)   // 4096

// Scratch (device globals; no allocation allowed)
__device__ float g_Q[BATCH * NHEADS * S_LEN * DK];
__device__ float g_K[BATCH * NHEADS * S_LEN * DK];
__device__ float g_V[BATCH * NHEADS * S_LEN * DK];
__device__ float g_O[MROWS * DMODEL];

// ===========================================================================
// PTX helpers (arch-agnostic: ldmatrix / mma.sync / cp.async)
// ===========================================================================
__device__ __forceinline__ uint32_t smem_u32(const void* p) {
    uint32_t a;
    asm("{ .reg .u64 t; cvta.to.shared.u64 t, %1; cvt.u32.u64 %0, t; }"
        : "=r"(a) : "l"(p));
    return a;
}

__device__ __forceinline__ void cp_async16(uint32_t dst, const void* src) {
    asm volatile("cp.async.cg.shared.global [%0], [%1], 16;"
                 :: "r"(dst), "l"(src));
}
#define CP_COMMIT() asm volatile("cp.async.commit_group;" ::: "memory")
#define CP_WAIT1()  asm volatile("cp.async.wait_group 1;" ::: "memory")
#define CP_WAIT0()  asm volatile("cp.async.wait_group 0;" ::: "memory")

#define LDSM_X4(r0, r1, r2, r3, addr)                                     \
    asm volatile("ldmatrix.sync.aligned.m8n8.x4.shared.b16 "              \
                 "{%0,%1,%2,%3}, [%4];"                                   \
                 : "=r"(r0), "=r"(r1), "=r"(r2), "=r"(r3) : "r"(addr))

// D += A @ B  (m16n8k8 tf32)
#define MMA_TF32(c, a0, a1, a2, a3, b0, b1)                               \
    asm volatile("mma.sync.aligned.m16n8k8.row.col.f32.tf32.tf32.f32 "    \
                 "{%0,%1,%2,%3},{%4,%5,%6,%7},{%8,%9},{%0,%1,%2,%3};"     \
                 : "+f"((c)[0]), "+f"((c)[1]), "+f"((c)[2]), "+f"((c)[3]) \
                 : "r"(a0), "r"(a1), "r"(a2), "r"(a3),                    \
                   "r"(b0), "r"(b1))

__device__ __forceinline__ uint32_t tf32_rna(float x) {
    uint32_t r;
    asm("cvt.rna.tf32.f32 %0, %1;" : "=r"(r) : "f"(x));
    return r;
}
// split f32 (bit pattern in u) into big/small tf32 parts
__device__ __forceinline__ void tf32_split(uint32_t u, uint32_t& big, uint32_t& sml) {
    float x = __uint_as_float(u);
    big = tf32_rna(x);
    sml = tf32_rna(x - __uint_as_float(big));
}

// ===========================================================================
// 3xTF32 mma.sync GEMM:  C[128x128] tile of  A(Mx1024) @ W(rows)^T
// mode 0=Q (RoPE+bhsd), 1=K (RoPE+bhsd), 2=V (bhsd), 3=O-proj (row-major out)
// 256 threads = 8 warps (2x4), warp tile 64x32, BK=32, cp.async double buffer.
// ===========================================================================
__global__ __launch_bounds__(256) void mma_gemm_kernel(
    const float* __restrict__ A_in,
    const float* __restrict__ W0,
    const float* __restrict__ W1,
    const float* __restrict__ W2,
    const int*   __restrict__ pos,
    float*       __restrict__ outp,
    int mode_sel)
{
    extern __shared__ char dynsmem[];

    const int mode = (mode_sel < 0) ? (int)blockIdx.z : mode_sel;
    const float* __restrict__ A = (mode == 3) ? (const float*)g_O : A_in;
    const float* __restrict__ W =
        (mode == 0) ? W0 : ((mode == 1) ? W1 : ((mode == 2) ? W2 : W0));

    const int t   = threadIdx.x;
    const int wid = t >> 5;
    const int lid = t & 31;
    const int wm  = wid >> 2;          // 0..1
    const int wn  = wid & 3;           // 0..3
    const int n0  = blockIdx.x * 128;
    const int m0  = blockIdx.y * 128;

    uint32_t raw = smem_u32(dynsmem);
    uint32_t pad = (1024u - (raw & 1023u)) & 1023u;
    const uint32_t sbase = raw + pad;

    float c[4][4][4];
#pragma unroll
    for (int i = 0; i < 4; i++)
#pragma unroll
        for (int j = 0; j < 4; j++)
#pragma unroll
            for (int k = 0; k < 4; k++) c[i][j][k] = 0.f;

    auto stage_load = [&](int buf, int k0) {
        const uint32_t sa = sbase + buf * 32768;
#pragma unroll
        for (int i = 0; i < 4; i++) {
            int idx = i * 256 + t;          // 0..1023
            int row = idx >> 3;
            int ch  = idx & 7;
            uint32_t off = (uint32_t)(row * 128 + ((ch ^ (row & 7)) << 4));
            cp_async16(sa + off,         A + (size_t)(m0 + row) * DMODEL + k0 + ch * 4);
            cp_async16(sa + 16384 + off, W + (size_t)(n0 + row) * DMODEL + k0 + ch * 4);
        }
        CP_COMMIT();
    };

    stage_load(0, 0);
    stage_load(1, 32);

    const int sub = lid >> 3;            // matrix index 0..3
    const int r   = lid & 7;
    const int a_row = wm * 64 + (sub & 1) * 8 + r;
    const int b_row = wn * 32 + (sub & 1) * 8 + r;
    const int chalf = sub >> 1;

    for (int s = 0; s < 32; s++) {
        const int buf = s & 1;
        if (s >= 30) { CP_WAIT0(); } else { CP_WAIT1(); }
        __syncthreads();

        const uint32_t As_a = sbase + buf * 32768;
        const uint32_t Bs_a = As_a + 16384;

#pragma unroll
        for (int ks = 0; ks < 4; ks++) {
            const int chunk = ks * 2 + chalf;
            uint32_t ab[4][4], as[4][4], bb[2][4], bs[2][4];
#pragma unroll
            for (int mi = 0; mi < 4; mi++) {
                int row = a_row + mi * 16;
                uint32_t addr = As_a + row * 128 + ((chunk ^ (row & 7)) << 4);
                uint32_t t0, t1, t2, t3;
                LDSM_X4(t0, t1, t2, t3, addr);
                tf32_split(t0, ab[mi][0], as[mi][0]);
                tf32_split(t1, ab[mi][1], as[mi][1]);
                tf32_split(t2, ab[mi][2], as[mi][2]);
                tf32_split(t3, ab[mi][3], as[mi][3]);
            }
#pragma unroll
            for (int nj = 0; nj < 2; nj++) {
                int row = b_row + nj * 16;
                uint32_t addr = Bs_a + row * 128 + ((chunk ^ (row & 7)) << 4);
                uint32_t t0, t1, t2, t3;
                LDSM_X4(t0, t1, t2, t3, addr);
                tf32_split(t0, bb[nj][0], bs[nj][0]);
                tf32_split(t1, bb[nj][1], bs[nj][1]);
                tf32_split(t2, bb[nj][2], bs[nj][2]);
                tf32_split(t3, bb[nj][3], bs[nj][3]);
            }
#pragma unroll
            for (int mi = 0; mi < 4; mi++)
#pragma unroll
                for (int nj = 0; nj < 2; nj++) {
                    // col group 0 (b regs 0,2) and col group 1 (b regs 1,3)
                    MMA_TF32(c[mi][2 * nj],
                             as[mi][0], as[mi][1], as[mi][2], as[mi][3],
                             bb[nj][0], bb[nj][2]);
                    MMA_TF32(c[mi][2 * nj],
                             ab[mi][0], ab[mi][1], ab[mi][2], ab[mi][3],
                             bs[nj][0], bs[nj][2]);
                    MMA_TF32(c[mi][2 * nj],
                             ab[mi][0], ab[mi][1], ab[mi][2], ab[mi][3],
                             bb[nj][0], bb[nj][2]);
                    MMA_TF32(c[mi][2 * nj + 1],
                             as[mi][0], as[mi][1], as[mi][2], as[mi][3],
                             bb[nj][1], bb[nj][3]);
                    MMA_TF32(c[mi][2 * nj + 1],
                             ab[mi][0], ab[mi][1], ab[mi][2], ab[mi][3],
                             bs[nj][1], bs[nj][3]);
                    MMA_TF32(c[mi][2 * nj + 1],
                             ab[mi][0], ab[mi][1], ab[mi][2], ab[mi][3],
                             bb[nj][1], bb[nj][3]);
                }
        }

        __syncthreads();
        if (s < 30) stage_load(buf, (s + 2) * 32);
    }

    // ---------------- epilogue ----------------
    const int rbase = m0 + wm * 64 + (lid >> 2);
    const int cbase = n0 + wn * 32 + (lid & 3) * 2;
    const float neg_lt = -logf(10000.0f) / 64.0f;

    if (mode == 3) {
#pragma unroll
        for (int mi = 0; mi < 4; mi++) {
#pragma unroll
            for (int nj = 0; nj < 4; nj++) {
                int row0 = rbase + mi * 16;
                int col  = cbase + nj * 8;
                *(float2*)(outp + (size_t)row0 * DMODEL + col) =
                    make_float2(c[mi][nj][0], c[mi][nj][1]);
                *(float2*)(outp + (size_t)(row0 + 8) * DMODEL + col) =
                    make_float2(c[mi][nj][2], c[mi][nj][3]);
            }
        }
    } else {
        float* base = (mode == 0) ? g_Q : (mode == 1) ? g_K : g_V;
#pragma unroll
        for (int mi = 0; mi < 4; mi++) {
            int row0 = rbase + mi * 16;
#pragma unroll
            for (int half = 0; half < 2; half++) {
                int row  = row0 + half * 8;
                int b    = row >> 11;
                int srow = row & (S_LEN - 1);
                float p  = (float)pos[srow];
#pragma unroll
                for (int nj = 0; nj < 4; nj++) {
                    int col = cbase + nj * 8;
                    int h   = col >> 6;
                    int d   = col & 63;
                    float x1 = c[mi][nj][half * 2];
                    float x2 = c[mi][nj][half * 2 + 1];
                    float* dst = base +
                        (((size_t)(b * NHEADS + h) * S_LEN + srow) * DK) + d;
                    if (mode == 2) {
                        *(float2*)dst = make_float2(x1, x2);
                    } else {
                        float fr = expf((float)d * neg_lt);
                        float sn, cs;
                        sincosf(p * fr, &sn, &cs);
                        *(float2*)dst = make_float2(x1 * cs - x2 * sn,
                                                    x1 * sn + x2 * cs);
                    }
                }
            }
        }
    }
}

// ---------------------------------------------------------------------------
// Flash attention (causal) — SIMT fp32 (unchanged).
// ---------------------------------------------------------------------------
__global__ __launch_bounds__(256) void attn_kernel()
{
    __shared__ float Qs [64 * 64];
    __shared__ float KPs[64 * 64];
    __shared__ float Vs [64 * 64];

    const int t  = threadIdx.x;
    const int tx = t & 15;
    const int ty = t >> 4;
    const int q0 = blockIdx.x * 64;
    const int h  = blockIdx.y;
    const int b  = blockIdx.z;
    const int bh = b * NHEADS + h;

    const float* __restrict__ Qp = g_Q + (size_t)bh * S_LEN * DK;
    const float* __restrict__ Kp = g_K + (size_t)bh * S_LEN * DK;
    const float* __restrict__ Vp = g_V + (size_t)bh * S_LEN * DK;

#pragma unroll
    for (int idx = t; idx < 1024; idx += 256) {
        int row = idx >> 4, d4 = (idx & 15) << 2;
        float4 v = *(const float4*)(Qp + (size_t)(q0 + row) * DK + d4);
        Qs[(d4 + 0) * 64 + row] = v.x;
        Qs[(d4 + 1) * 64 + row] = v.y;
        Qs[(d4 + 2) * 64 + row] = v.z;
        Qs[(d4 + 3) * 64 + row] = v.w;
    }

    float acc[4][4];
    float m[4], l[4];
#pragma unroll
    for (int i = 0; i < 4; i++) {
        m[i] = -1e30f;
        l[i] = 0.f;
#pragma unroll
        for (int j = 0; j < 4; j++) acc[i][j] = 0.f;
    }

    const int ntiles = (q0 >> 6) + 1;
    for (int kt = 0; kt < ntiles; kt++) {
        const int k0 = kt * 64;
        __syncthreads();

#pragma unroll
        for (int idx = t; idx < 1024; idx += 256) {
            int row = idx >> 4, d4 = (idx & 15) << 2;
            float4 kv = *(const float4*)(Kp + (size_t)(k0 + row) * DK + d4);
            KPs[(d4 + 0) * 64 + row] = kv.x;
            KPs[(d4 + 1) * 64 + row] = kv.y;
            KPs[(d4 + 2) * 64 + row] = kv.z;
            KPs[(d4 + 3) * 64 + row] = kv.w;
            float4 vv = *(const float4*)(Vp + (size_t)(k0 + row) * DK + d4);
            *(float4*)(Vs + row * 64 + d4) = vv;
        }
        __syncthreads();

        float sreg[4][4];
#pragma unroll
        for (int i = 0; i < 4; i++)
#pragma unroll
            for (int j = 0; j < 4; j++) sreg[i][j] = 0.f;

#pragma unroll
        for (int kk = 0; kk < 64; kk++) {
            float4 qv = *(const float4*)(Qs  + kk * 64 + ty * 4);
            float4 kv = *(const float4*)(KPs + kk * 64 + tx * 4);
            float qf[4] = {qv.x, qv.y, qv.z, qv.w};
            float kf[4] = {kv.x, kv.y, kv.z, kv.w};
#pragma unroll
            for (int i = 0; i < 4; i++)
#pragma unroll
                for (int j = 0; j < 4; j++) sreg[i][j] += qf[i] * kf[j];
        }

        const bool diag = (k0 == q0);
#pragma unroll
        for (int i = 0; i < 4; i++)
#pragma unroll
            for (int j = 0; j < 4; j++) {
                float v = sreg[i][j] * 0.125f;
                if (diag && (tx * 4 + j) > (ty * 4 + i)) v = -1e30f;
                sreg[i][j] = v;
            }

#pragma unroll
        for (int i = 0; i < 4; i++) {
            float mloc = fmaxf(fmaxf(sreg[i][0], sreg[i][1]),
                               fmaxf(sreg[i][2], sreg[i][3]));
            mloc = fmaxf(mloc, __shfl_xor_sync(0xffffffffu, mloc, 1));
            mloc = fmaxf(mloc, __shfl_xor_sync(0xffffffffu, mloc, 2));
            mloc = fmaxf(mloc, __shfl_xor_sync(0xffffffffu, mloc, 4));
            mloc = fmaxf(mloc, __shfl_xor_sync(0xffffffffu, mloc, 8));
            float mn = fmaxf(m[i], mloc);
            float al = __expf(m[i] - mn);
            m[i] = mn;
            float ls = 0.f;
#pragma unroll
            for (int j = 0; j < 4; j++) {
                sreg[i][j] = __expf(sreg[i][j] - mn);
                ls += sreg[i][j];
            }
            ls += __shfl_xor_sync(0xffffffffu, ls, 1);
            ls += __shfl_xor_sync(0xffffffffu, ls, 2);
            ls += __shfl_xor_sync(0xffffffffu, ls, 4);
            ls += __shfl_xor_sync(0xffffffffu, ls, 8);
            l[i] = l[i] * al + ls;
#pragma unroll
            for (int j = 0; j < 4; j++) acc[i][j] *= al;
        }

        __syncthreads();
#pragma unroll
        for (int i = 0; i < 4; i++)
            *(float4*)(KPs + (ty * 4 + i) * 64 + tx * 4) =
                make_float4(sreg[i][0], sreg[i][1], sreg[i][2], sreg[i][3]);
        __syncthreads();

#pragma unroll
        for (int jj = 0; jj < 64; jj++) {
            float4 vv = *(const float4*)(Vs + jj * 64 + tx * 4);
#pragma unroll
            for (int i = 0; i < 4; i++) {
                float p = KPs[(ty * 4 + i) * 64 + jj];
                acc[i][0] += p * vv.x;
                acc[i][1] += p * vv.y;
                acc[i][2] += p * vv.z;
                acc[i][3] += p * vv.w;
            }
        }
    }

#pragma unroll
    for (int i = 0; i < 4; i++) {
        float inv = 1.0f / l[i];
        int srow = q0 + ty * 4 + i;
        *(float4*)(g_O + (size_t)(b * S_LEN + srow) * DMODEL + h * DK + tx * 4) =
            make_float4(acc[i][0] * inv, acc[i][1] * inv,
                        acc[i][2] * inv, acc[i][3] * inv);
    }
}

// ---------------------------------------------------------------------------
extern "C" void kernel_launch(void* const* d_in, const int* in_sizes, int n_in,
                              void* d_out, int out_size)
{
    const float* x   = (const float*)d_in[0];
    const int*   pos = (const int*)  d_in[1];
    const float* Wq  = (const float*)d_in[2];
    const float* Wk  = (const float*)d_in[3];
    const float* Wv  = (const float*)d_in[4];
    const float* Wo  = (const float*)d_in[5];
    float* out = (float*)d_out;

    const int DYN = 2 * 32768 + 1024;
    cudaFuncSetAttribute(mma_gemm_kernel,
                         cudaFuncAttributeMaxDynamicSharedMemorySize, DYN);

    // QKV projections + RoPE (3xTF32 mma.sync)
    mma_gemm_kernel<<<dim3(DMODEL / 128, MROWS / 128, 3), 256, DYN>>>(
        x, Wq, Wk, Wv, pos, nullptr, -1);
    // Causal flash attention (fp32 SIMT)
    attn_kernel<<<dim3(S_LEN / 64, NHEADS, BATCH), 256>>>();
    // Output projection (3xTF32 mma.sync)
    mma_gemm_kernel<<<dim3(DMODEL / 128, MROWS / 128, 1), 256, DYN>>>(
        nullptr, Wo, Wo, Wo, pos, out, 3);
}

// round 5
// speedup vs baseline: 1.5783x; 1.1818x over previous
#include <cuda_runtime.h>
#include <math.h>
#include <stdint.h>

#define S_LEN  2048
#define DMODEL 1024
#define NHEADS 16
#define DK     64
#define BATCH  2
#define MROWS  (BATCH * S_LEN)   // 4096

// Scratch (device globals; no allocation allowed)
__device__ float g_Q[BATCH * NHEADS * S_LEN * DK];
__device__ float g_K[BATCH * NHEADS * S_LEN * DK];
__device__ float g_V[BATCH * NHEADS * S_LEN * DK];
__device__ float g_O[MROWS * DMODEL];

// ===========================================================================
// PTX helpers (arch-agnostic: ldmatrix / mma.sync / cp.async)
// ===========================================================================
__device__ __forceinline__ uint32_t smem_u32(const void* p) {
    uint32_t a;
    asm("{ .reg .u64 t; cvta.to.shared.u64 t, %1; cvt.u32.u64 %0, t; }"
        : "=r"(a) : "l"(p));
    return a;
}

__device__ __forceinline__ void cp_async16(uint32_t dst, const void* src) {
    asm volatile("cp.async.cg.shared.global [%0], [%1], 16;"
                 :: "r"(dst), "l"(src));
}
#define CP_COMMIT() asm volatile("cp.async.commit_group;" ::: "memory")
#define CP_WAIT1()  asm volatile("cp.async.wait_group 1;" ::: "memory")
#define CP_WAIT0()  asm volatile("cp.async.wait_group 0;" ::: "memory")

#define LDSM_X4(r0, r1, r2, r3, addr)                                     \
    asm volatile("ldmatrix.sync.aligned.m8n8.x4.shared.b16 "              \
                 "{%0,%1,%2,%3}, [%4];"                                   \
                 : "=r"(r0), "=r"(r1), "=r"(r2), "=r"(r3) : "r"(addr))

// D += A @ B  (m16n8k8 tf32)
#define MMA_TF32(c, a0, a1, a2, a3, b0, b1)                               \
    asm volatile("mma.sync.aligned.m16n8k8.row.col.f32.tf32.tf32.f32 "    \
                 "{%0,%1,%2,%3},{%4,%5,%6,%7},{%8,%9},{%0,%1,%2,%3};"     \
                 : "+f"((c)[0]), "+f"((c)[1]), "+f"((c)[2]), "+f"((c)[3]) \
                 : "r"(a0), "r"(a1), "r"(a2), "r"(a3),                    \
                   "r"(b0), "r"(b1))

__device__ __forceinline__ uint32_t tf32_rna(float x) {
    uint32_t r;
    asm("cvt.rna.tf32.f32 %0, %1;" : "=r"(r) : "f"(x));
    return r;
}
__device__ __forceinline__ void tf32_split(uint32_t u, uint32_t& big, uint32_t& sml) {
    float x = __uint_as_float(u);
    big = tf32_rna(x);
    sml = tf32_rna(x - __uint_as_float(big));
}

// ===========================================================================
// 3xTF32 mma.sync GEMM (unchanged from round 4, validated)
// ===========================================================================
__global__ __launch_bounds__(256) void mma_gemm_kernel(
    const float* __restrict__ A_in,
    const float* __restrict__ W0,
    const float* __restrict__ W1,
    const float* __restrict__ W2,
    const int*   __restrict__ pos,
    float*       __restrict__ outp,
    int mode_sel)
{
    extern __shared__ char dynsmem[];

    const int mode = (mode_sel < 0) ? (int)blockIdx.z : mode_sel;
    const float* __restrict__ A = (mode == 3) ? (const float*)g_O : A_in;
    const float* __restrict__ W =
        (mode == 0) ? W0 : ((mode == 1) ? W1 : ((mode == 2) ? W2 : W0));

    const int t   = threadIdx.x;
    const int wid = t >> 5;
    const int lid = t & 31;
    const int wm  = wid >> 2;
    const int wn  = wid & 3;
    const int n0  = blockIdx.x * 128;
    const int m0  = blockIdx.y * 128;

    uint32_t raw = smem_u32(dynsmem);
    uint32_t pad = (1024u - (raw & 1023u)) & 1023u;
    const uint32_t sbase = raw + pad;

    float c[4][4][4];
#pragma unroll
    for (int i = 0; i < 4; i++)
#pragma unroll
        for (int j = 0; j < 4; j++)
#pragma unroll
            for (int k = 0; k < 4; k++) c[i][j][k] = 0.f;

    auto stage_load = [&](int buf, int k0) {
        const uint32_t sa = sbase + buf * 32768;
#pragma unroll
        for (int i = 0; i < 4; i++) {
            int idx = i * 256 + t;
            int row = idx >> 3;
            int ch  = idx & 7;
            uint32_t off = (uint32_t)(row * 128 + ((ch ^ (row & 7)) << 4));
            cp_async16(sa + off,         A + (size_t)(m0 + row) * DMODEL + k0 + ch * 4);
            cp_async16(sa + 16384 + off, W + (size_t)(n0 + row) * DMODEL + k0 + ch * 4);
        }
        CP_COMMIT();
    };

    stage_load(0, 0);
    stage_load(1, 32);

    const int sub = lid >> 3;
    const int r   = lid & 7;
    const int a_row = wm * 64 + (sub & 1) * 8 + r;
    const int b_row = wn * 32 + (sub & 1) * 8 + r;
    const int chalf = sub >> 1;

    for (int s = 0; s < 32; s++) {
        const int buf = s & 1;
        if (s >= 30) { CP_WAIT0(); } else { CP_WAIT1(); }
        __syncthreads();

        const uint32_t As_a = sbase + buf * 32768;
        const uint32_t Bs_a = As_a + 16384;

#pragma unroll
        for (int ks = 0; ks < 4; ks++) {
            const int chunk = ks * 2 + chalf;
            uint32_t ab[4][4], as[4][4], bb[2][4], bs[2][4];
#pragma unroll
            for (int mi = 0; mi < 4; mi++) {
                int row = a_row + mi * 16;
                uint32_t addr = As_a + row * 128 + ((chunk ^ (row & 7)) << 4);
                uint32_t t0, t1, t2, t3;
                LDSM_X4(t0, t1, t2, t3, addr);
                tf32_split(t0, ab[mi][0], as[mi][0]);
                tf32_split(t1, ab[mi][1], as[mi][1]);
                tf32_split(t2, ab[mi][2], as[mi][2]);
                tf32_split(t3, ab[mi][3], as[mi][3]);
            }
#pragma unroll
            for (int nj = 0; nj < 2; nj++) {
                int row = b_row + nj * 16;
                uint32_t addr = Bs_a + row * 128 + ((chunk ^ (row & 7)) << 4);
                uint32_t t0, t1, t2, t3;
                LDSM_X4(t0, t1, t2, t3, addr);
                tf32_split(t0, bb[nj][0], bs[nj][0]);
                tf32_split(t1, bb[nj][1], bs[nj][1]);
                tf32_split(t2, bb[nj][2], bs[nj][2]);
                tf32_split(t3, bb[nj][3], bs[nj][3]);
            }
#pragma unroll
            for (int mi = 0; mi < 4; mi++)
#pragma unroll
                for (int nj = 0; nj < 2; nj++) {
                    MMA_TF32(c[mi][2 * nj],
                             as[mi][0], as[mi][1], as[mi][2], as[mi][3],
                             bb[nj][0], bb[nj][2]);
                    MMA_TF32(c[mi][2 * nj],
                             ab[mi][0], ab[mi][1], ab[mi][2], ab[mi][3],
                             bs[nj][0], bs[nj][2]);
                    MMA_TF32(c[mi][2 * nj],
                             ab[mi][0], ab[mi][1], ab[mi][2], ab[mi][3],
                             bb[nj][0], bb[nj][2]);
                    MMA_TF32(c[mi][2 * nj + 1],
                             as[mi][0], as[mi][1], as[mi][2], as[mi][3],
                             bb[nj][1], bb[nj][3]);
                    MMA_TF32(c[mi][2 * nj + 1],
                             ab[mi][0], ab[mi][1], ab[mi][2], ab[mi][3],
                             bs[nj][1], bs[nj][3]);
                    MMA_TF32(c[mi][2 * nj + 1],
                             ab[mi][0], ab[mi][1], ab[mi][2], ab[mi][3],
                             bb[nj][1], bb[nj][3]);
                }
        }

        __syncthreads();
        if (s < 30) stage_load(buf, (s + 2) * 32);
    }

    const int rbase = m0 + wm * 64 + (lid >> 2);
    const int cbase = n0 + wn * 32 + (lid & 3) * 2;
    const float neg_lt = -logf(10000.0f) / 64.0f;

    if (mode == 3) {
#pragma unroll
        for (int mi = 0; mi < 4; mi++) {
#pragma unroll
            for (int nj = 0; nj < 4; nj++) {
                int row0 = rbase + mi * 16;
                int col  = cbase + nj * 8;
                *(float2*)(outp + (size_t)row0 * DMODEL + col) =
                    make_float2(c[mi][nj][0], c[mi][nj][1]);
                *(float2*)(outp + (size_t)(row0 + 8) * DMODEL + col) =
                    make_float2(c[mi][nj][2], c[mi][nj][3]);
            }
        }
    } else {
        float* base = (mode == 0) ? g_Q : (mode == 1) ? g_K : g_V;
#pragma unroll
        for (int mi = 0; mi < 4; mi++) {
            int row0 = rbase + mi * 16;
#pragma unroll
            for (int half = 0; half < 2; half++) {
                int row  = row0 + half * 8;
                int b    = row >> 11;
                int srow = row & (S_LEN - 1);
                float p  = (float)pos[srow];
#pragma unroll
                for (int nj = 0; nj < 4; nj++) {
                    int col = cbase + nj * 8;
                    int h   = col >> 6;
                    int d   = col & 63;
                    float x1 = c[mi][nj][half * 2];
                    float x2 = c[mi][nj][half * 2 + 1];
                    float* dst = base +
                        (((size_t)(b * NHEADS + h) * S_LEN + srow) * DK) + d;
                    if (mode == 2) {
                        *(float2*)dst = make_float2(x1, x2);
                    } else {
                        float fr = expf((float)d * neg_lt);
                        float sn, cs;
                        sincosf(p * fr, &sn, &cs);
                        *(float2*)dst = make_float2(x1 * cs - x2 * sn,
                                                    x1 * sn + x2 * cs);
                    }
                }
            }
        }
    }
}

// ===========================================================================
// Tensor-core flash attention (causal), 3xTF32.
// CTA: 128 q-rows of one (b,h). 8 warps, 16 q-rows each, kv tiles of 64.
// Smem: Qs 32KB (persistent), Ps 32KB, Ks 16KB, Vts 16KB (transposed).
// ===========================================================================
__global__ __launch_bounds__(256) void attn_mma_kernel()
{
    extern __shared__ char dynsmem[];

    const int t   = threadIdx.x;
    const int wid = t >> 5;
    const int lid = t & 31;
    const int q0  = blockIdx.x * 128;
    const int bh  = blockIdx.y;
    const int b   = bh >> 4;
    const int h   = bh & 15;

    const float* __restrict__ Qp = g_Q + (size_t)bh * S_LEN * DK;
    const float* __restrict__ Kp = g_K + (size_t)bh * S_LEN * DK;
    const float* __restrict__ Vp = g_V + (size_t)bh * S_LEN * DK;

    uint32_t raw = smem_u32(dynsmem);
    uint32_t pad = (1024u - (raw & 1023u)) & 1023u;
    char*    sp  = dynsmem + pad;
    const uint32_t sQ = raw + pad;
    const uint32_t sP = sQ + 32768;
    const uint32_t sK = sQ + 65536;
    const uint32_t sV = sQ + 81920;
    char* spP = sp + 32768;
    char* spK = sp + 65536;
    char* spV = sp + 81920;

    // Q tile 128x64 f32, swizzled rows of 256B (16 chunks)
#pragma unroll
    for (int i = 0; i < 8; i++) {
        int idx = i * 256 + t, row = idx >> 4, ch = idx & 15;
        float4 v = *(const float4*)(Qp + (size_t)(q0 + row) * DK + ch * 4);
        *(float4*)(sp + row * 256 + ((ch ^ (row & 7)) << 4)) = v;
    }

    float o[8][4];
#pragma unroll
    for (int i = 0; i < 8; i++)
#pragma unroll
        for (int j = 0; j < 4; j++) o[i][j] = 0.f;
    float mrow[2] = {-1e30f, -1e30f};
    float lrow[2] = {0.f, 0.f};

    const int ntiles = (q0 >> 6) + 2;

    // prefetch tile 0 into regs
    float4 kreg[4], vreg[4];
#pragma unroll
    for (int i = 0; i < 4; i++) {
        int idx = i * 256 + t, row = idx >> 4, ch = idx & 15;
        kreg[i] = *(const float4*)(Kp + (size_t)row * DK + ch * 4);
        vreg[i] = *(const float4*)(Vp + (size_t)row * DK + ch * 4);
    }

    const int lrow8 = ((lid >> 3) & 1) * 8 + (lid & 7);
    const int chalf = lid >> 4;

    for (int kt = 0; kt < ntiles; kt++) {
        __syncthreads();   // previous tile's smem reads finished
        // store K (swizzled) and V (transposed, d-major) tiles
#pragma unroll
        for (int i = 0; i < 4; i++) {
            int idx = i * 256 + t, row = idx >> 4, ch = idx & 15;
            *(float4*)(spK + row * 256 + ((ch ^ (row & 7)) << 4)) = kreg[i];
            int kv = row, d0 = ch * 4;
            float vv[4] = {vreg[i].x, vreg[i].y, vreg[i].z, vreg[i].w};
#pragma unroll
            for (int j = 0; j < 4; j++) {
                int d = d0 + j;
                *(float*)(spV + d * 256 + (((kv >> 2) ^ (d & 7)) << 4) +
                          (kv & 3) * 4) = vv[j];
            }
        }
        __syncthreads();

        // prefetch next tile (overlaps with MMA below)
        if (kt + 1 < ntiles) {
            const int k0n = (kt + 1) * 64;
#pragma unroll
            for (int i = 0; i < 4; i++) {
                int idx = i * 256 + t, row = idx >> 4, ch = idx & 15;
                kreg[i] = *(const float4*)(Kp + (size_t)(k0n + row) * DK + ch * 4);
                vreg[i] = *(const float4*)(Vp + (size_t)(k0n + row) * DK + ch * 4);
            }
        }

        // ---- S = Q K^T (3xTF32) ----
        float s[8][4];
#pragma unroll
        for (int i = 0; i < 8; i++)
#pragma unroll
            for (int j = 0; j < 4; j++) s[i][j] = 0.f;

        for (int ks = 0; ks < 8; ks++) {
            const int ch = ks * 2 + chalf;
            int arow = 16 * wid + lrow8;
            uint32_t aaddr = sQ + arow * 256 + ((ch ^ (arow & 7)) << 4);
            uint32_t t0, t1, t2, t3;
            LDSM_X4(t0, t1, t2, t3, aaddr);
            uint32_t qb[4], qsm[4];
            tf32_split(t0, qb[0], qsm[0]);
            tf32_split(t1, qb[1], qsm[1]);
            tf32_split(t2, qb[2], qsm[2]);
            tf32_split(t3, qb[3], qsm[3]);
#pragma unroll
            for (int nj = 0; nj < 4; nj++) {
                int brow = nj * 16 + lrow8;
                uint32_t baddr = sK + brow * 256 + ((ch ^ (brow & 7)) << 4);
                uint32_t u0, u1, u2, u3;
                LDSM_X4(u0, u1, u2, u3, baddr);
                uint32_t b0b, b0s, b1b, b1s, b2b, b2s, b3b, b3s;
                tf32_split(u0, b0b, b0s);
                tf32_split(u1, b1b, b1s);
                tf32_split(u2, b2b, b2s);
                tf32_split(u3, b3b, b3s);
                MMA_TF32(s[2 * nj], qsm[0], qsm[1], qsm[2], qsm[3], b0b, b2b);
                MMA_TF32(s[2 * nj], qb[0], qb[1], qb[2], qb[3], b0s, b2s);
                MMA_TF32(s[2 * nj], qb[0], qb[1], qb[2], qb[3], b0b, b2b);
                MMA_TF32(s[2 * nj + 1], qsm[0], qsm[1], qsm[2], qsm[3], b1b, b3b);
                MMA_TF32(s[2 * nj + 1], qb[0], qb[1], qb[2], qb[3], b1s, b3s);
                MMA_TF32(s[2 * nj + 1], qb[0], qb[1], qb[2], qb[3], b1b, b3b);
            }
        }

        // ---- scale + causal mask ----
        const int k0 = kt * 64;
        const int qA = q0 + 16 * wid + (lid >> 2);
#pragma unroll
        for (int nf = 0; nf < 8; nf++) {
            int colb = k0 + nf * 8 + 2 * (lid & 3);
#pragma unroll
            for (int e = 0; e < 4; e++) {
                int q  = qA + ((e >> 1) << 3);
                int kv = colb + (e & 1);
                float v = s[nf][e] * 0.125f;
                s[nf][e] = (kv > q) ? -1e30f : v;
            }
        }

        // ---- online softmax (rows: half 0 -> qA, half 1 -> qA+8) ----
#pragma unroll
        for (int half = 0; half < 2; half++) {
            float ml = -1e30f;
#pragma unroll
            for (int nf = 0; nf < 8; nf++)
                ml = fmaxf(ml, fmaxf(s[nf][2 * half], s[nf][2 * half + 1]));
            ml = fmaxf(ml, __shfl_xor_sync(0xffffffffu, ml, 1));
            ml = fmaxf(ml, __shfl_xor_sync(0xffffffffu, ml, 2));
            float mn = fmaxf(mrow[half], ml);
            float al = __expf(mrow[half] - mn);
            mrow[half] = mn;
            float ls = 0.f;
#pragma unroll
            for (int nf = 0; nf < 8; nf++) {
                float e0 = __expf(s[nf][2 * half] - mn);
                float e1 = __expf(s[nf][2 * half + 1] - mn);
                s[nf][2 * half] = e0;
                s[nf][2 * half + 1] = e1;
                ls += e0 + e1;
            }
            ls += __shfl_xor_sync(0xffffffffu, ls, 1);
            ls += __shfl_xor_sync(0xffffffffu, ls, 2);
            lrow[half] = lrow[half] * al + ls;
#pragma unroll
            for (int nf = 0; nf < 8; nf++) {
                o[nf][2 * half] *= al;
                o[nf][2 * half + 1] *= al;
            }
        }

        // ---- store P (own 16 rows) ----
        {
            int pr0 = 16 * wid + (lid >> 2), pr1 = pr0 + 8;
#pragma unroll
            for (int nf = 0; nf < 8; nf++) {
                int col = nf * 8 + 2 * (lid & 3);
                int cc = col >> 2, cl = col & 3;
                *(float2*)(spP + pr0 * 256 + ((cc ^ (pr0 & 7)) << 4) + cl * 4) =
                    make_float2(s[nf][0], s[nf][1]);
                *(float2*)(spP + pr1 * 256 + ((cc ^ (pr1 & 7)) << 4) + cl * 4) =
                    make_float2(s[nf][2], s[nf][3]);
            }
        }
        __syncwarp();

        // ---- O += P V (3xTF32) ----
        for (int ks = 0; ks < 8; ks++) {
            const int ch = ks * 2 + chalf;
            int arow = 16 * wid + lrow8;
            uint32_t aaddr = sP + arow * 256 + ((ch ^ (arow & 7)) << 4);
            uint32_t t0, t1, t2, t3;
            LDSM_X4(t0, t1, t2, t3, aaddr);
            uint32_t pb[4], psm[4];
            tf32_split(t0, pb[0], psm[0]);
            tf32_split(t1, pb[1], psm[1]);
            tf32_split(t2, pb[2], psm[2]);
            tf32_split(t3, pb[3], psm[3]);
#pragma unroll
            for (int nj = 0; nj < 4; nj++) {
                int brow = nj * 16 + lrow8;
                uint32_t baddr = sV + brow * 256 + ((ch ^ (brow & 7)) << 4);
                uint32_t u0, u1, u2, u3;
                LDSM_X4(u0, u1, u2, u3, baddr);
                uint32_t b0b, b0s, b1b, b1s, b2b, b2s, b3b, b3s;
                tf32_split(u0, b0b, b0s);
                tf32_split(u1, b1b, b1s);
                tf32_split(u2, b2b, b2s);
                tf32_split(u3, b3b, b3s);
                MMA_TF32(o[2 * nj], psm[0], psm[1], psm[2], psm[3], b0b, b2b);
                MMA_TF32(o[2 * nj], pb[0], pb[1], pb[2], pb[3], b0s, b2s);
                MMA_TF32(o[2 * nj], pb[0], pb[1], pb[2], pb[3], b0b, b2b);
                MMA_TF32(o[2 * nj + 1], psm[0], psm[1], psm[2], psm[3], b1b, b3b);
                MMA_TF32(o[2 * nj + 1], pb[0], pb[1], pb[2], pb[3], b1s, b3s);
                MMA_TF32(o[2 * nj + 1], pb[0], pb[1], pb[2], pb[3], b1b, b3b);
            }
        }
    }

    // ---- normalize + write to g_O (b*s, D) ----
    const float i0 = 1.0f / lrow[0];
    const float i1 = 1.0f / lrow[1];
    const int qA = q0 + 16 * wid + (lid >> 2);
#pragma unroll
    for (int nf = 0; nf < 8; nf++) {
        int col = h * 64 + nf * 8 + 2 * (lid & 3);
        *(float2*)(g_O + (size_t)(b * S_LEN + qA) * DMODEL + col) =
            make_float2(o[nf][0] * i0, o[nf][1] * i0);
        *(float2*)(g_O + (size_t)(b * S_LEN + qA + 8) * DMODEL + col) =
            make_float2(o[nf][2] * i1, o[nf][3] * i1);
    }
}

// ---------------------------------------------------------------------------
extern "C" void kernel_launch(void* const* d_in, const int* in_sizes, int n_in,
                              void* d_out, int out_size)
{
    const float* x   = (const float*)d_in[0];
    const int*   pos = (const int*)  d_in[1];
    const float* Wq  = (const float*)d_in[2];
    const float* Wk  = (const float*)d_in[3];
    const float* Wv  = (const float*)d_in[4];
    const float* Wo  = (const float*)d_in[5];
    float* out = (float*)d_out;

    const int DYN_GEMM = 2 * 32768 + 1024;
    const int DYN_ATTN = 98304 + 1024;
    cudaFuncSetAttribute(mma_gemm_kernel,
                         cudaFuncAttributeMaxDynamicSharedMemorySize, DYN_GEMM);
    cudaFuncSetAttribute(attn_mma_kernel,
                         cudaFuncAttributeMaxDynamicSharedMemorySize, DYN_ATTN);

    // QKV projections + RoPE (3xTF32 mma.sync)
    mma_gemm_kernel<<<dim3(DMODEL / 128, MROWS / 128, 3), 256, DYN_GEMM>>>(
        x, Wq, Wk, Wv, pos, nullptr, -1);
    // Causal flash attention (3xTF32 mma.sync)
    attn_mma_kernel<<<dim3(S_LEN / 128, BATCH * NHEADS), 256, DYN_ATTN>>>();
    // Output projection (3xTF32 mma.sync)
    mma_gemm_kernel<<<dim3(DMODEL / 128, MROWS / 128, 1), 256, DYN_GEMM>>>(
        nullptr, Wo, Wo, Wo, pos, out, 3);
}

// round 6
// speedup vs baseline: 3.0729x; 1.9470x over previous
#include <cuda_runtime.h>
#include <cuda_bf16.h>
#include <math.h>
#include <stdint.h>

#define S_LEN  2048
#define DMODEL 1024
#define NHEADS 16
#define DK     64
#define BATCH  2
#define MROWS  (BATCH * S_LEN)   // 4096

// ---------------------------------------------------------------------------
// Device-global scratch (no allocation allowed).
// Split layout convention for a row of N f32: per 32-col block kb:
//   32 uint32 = [16 u32 hi pairs | 16 u32 mid pairs]  (bf16x2 per u32)
// ---------------------------------------------------------------------------
__device__ uint32_t g_Xs[MROWS * DMODEL];            // x split   (row: 1024 u32)
__device__ uint32_t g_Ws[4][DMODEL * DMODEL];        // Wq,Wk,Wv,Wo split
__device__ uint32_t g_Qs[BATCH * NHEADS * S_LEN * 64]; // Q split (row: 64 u32 = 32 hi | 32 mid)
__device__ uint32_t g_Ks[BATCH * NHEADS * S_LEN * 64]; // K split
__device__ float    g_V [BATCH * NHEADS * S_LEN * DK]; // V fp32 (b,h,s,d)
__device__ uint32_t g_Os[MROWS * DMODEL];            // attention out, split

// ===========================================================================
// PTX helpers
// ===========================================================================
__device__ __forceinline__ uint32_t smem_u32(const void* p) {
    uint32_t a;
    asm("{ .reg .u64 t; cvta.to.shared.u64 t, %1; cvt.u32.u64 %0, t; }"
        : "=r"(a) : "l"(p));
    return a;
}
__device__ __forceinline__ void cp_async16(uint32_t dst, const void* src) {
    asm volatile("cp.async.cg.shared.global [%0], [%1], 16;"
                 :: "r"(dst), "l"(src));
}
#define CP_COMMIT() asm volatile("cp.async.commit_group;" ::: "memory")
#define CP_WAIT1()  asm volatile("cp.async.wait_group 1;" ::: "memory")
#define CP_WAIT0()  asm volatile("cp.async.wait_group 0;" ::: "memory")

#define LDSM_X4(r0, r1, r2, r3, addr)                                     \
    asm volatile("ldmatrix.sync.aligned.m8n8.x4.shared.b16 "              \
                 "{%0,%1,%2,%3}, [%4];"                                   \
                 : "=r"(r0), "=r"(r1), "=r"(r2), "=r"(r3) : "r"(addr))

// D += A @ B  (m16n8k16 bf16, f32 accum)
#define MMA_BF16(c, a, b0, b1)                                            \
    asm volatile("mma.sync.aligned.m16n8k16.row.col.f32.bf16.bf16.f32 "   \
                 "{%0,%1,%2,%3},{%4,%5,%6,%7},{%8,%9},{%0,%1,%2,%3};"     \
                 : "+f"((c)[0]), "+f"((c)[1]), "+f"((c)[2]), "+f"((c)[3]) \
                 : "r"((a)[0]), "r"((a)[1]), "r"((a)[2]), "r"((a)[3]),    \
                   "r"(b0), "r"(b1))

// split pair (x0 -> low half, x1 -> high half) into hi/mid bf16x2
__device__ __forceinline__ void bf16_split2(float x0, float x1,
                                            uint32_t& hi2, uint32_t& mid2) {
    uint32_t h;
    asm("cvt.rn.bf16x2.f32 %0, %2, %1;" : "=r"(h) : "f"(x0), "f"(x1));
    float h0 = __uint_as_float(h << 16);
    float h1 = __uint_as_float(h & 0xffff0000u);
    float m0 = x0 - h0, m1 = x1 - h1;
    uint32_t m;
    asm("cvt.rn.bf16x2.f32 %0, %2, %1;" : "=r"(m) : "f"(m0), "f"(m1));
    hi2 = h; mid2 = m;
}

// ===========================================================================
// Split prep: f32 row-major [rows][1024] -> split u32 [rows][1024]
// which: 0 = x -> g_Xs, 1..4 -> g_Ws[which-1]
// ===========================================================================
__global__ __launch_bounds__(256) void split_kernel(const float* __restrict__ in,
                                                    int which, int n4) {
    int idx = blockIdx.x * 256 + threadIdx.x;
    if (idx >= n4) return;
    uint32_t* out = (which == 0) ? g_Xs : g_Ws[which - 1];
    int r  = idx >> 8;
    int p4 = idx & 255;
    int kb = p4 >> 3, q = p4 & 7;
    float4 v = *(const float4*)(in + (size_t)idx * 4);
    uint32_t h0, m0, h1, m1;
    bf16_split2(v.x, v.y, h0, m0);
    bf16_split2(v.z, v.w, h1, m1);
    uint32_t* o = out + (size_t)r * 1024 + kb * 32;
    *(uint2*)(o + 2 * q)      = make_uint2(h0, h1);
    *(uint2*)(o + 16 + 2 * q) = make_uint2(m0, m1);
}

// ===========================================================================
// 3xBF16 mma.sync GEMM:  C[128x128] tile of  A @ W^T  (both pre-split)
// mode 0=Q (RoPE + split bhsd), 1=K (same), 2=V (f32 bhsd), 3=O-proj (f32 out)
// 256 threads = 8 warps (2x4), warp tile 64x32, BK=32, cp.async double buffer.
// Smem tile: 128 rows x 128B ([hi 64B | mid 64B], 16B-chunk XOR swizzle).
// ===========================================================================
__global__ __launch_bounds__(256) void mma_gemm_kernel(
    const int* __restrict__ pos,
    float*     __restrict__ outp,
    int mode_sel)
{
    extern __shared__ char dynsmem[];

    const int mode = (mode_sel < 0) ? (int)blockIdx.z : mode_sel;
    const uint32_t* __restrict__ A = (mode == 3) ? g_Os : g_Xs;
    const uint32_t* __restrict__ W = g_Ws[mode];

    const int t   = threadIdx.x;
    const int wid = t >> 5;
    const int lid = t & 31;
    const int wm  = wid >> 2;
    const int wn  = wid & 3;
    const int n0  = blockIdx.x * 128;
    const int m0  = blockIdx.y * 128;

    uint32_t raw = smem_u32(dynsmem);
    uint32_t pad = (1024u - (raw & 1023u)) & 1023u;
    const uint32_t sbase = raw + pad;

    float c[4][4][4];
#pragma unroll
    for (int i = 0; i < 4; i++)
#pragma unroll
        for (int j = 0; j < 4; j++)
#pragma unroll
            for (int k = 0; k < 4; k++) c[i][j][k] = 0.f;

    auto stage_load = [&](int buf, int s) {
        const uint32_t sa = sbase + buf * 32768;
#pragma unroll
        for (int i = 0; i < 4; i++) {
            int idx = i * 256 + t;
            int row = idx >> 3;
            int ch  = idx & 7;
            uint32_t off = (uint32_t)(row * 128 + ((ch ^ (row & 7)) << 4));
            cp_async16(sa + off,         A + (size_t)(m0 + row) * 1024 + s * 32 + ch * 4);
            cp_async16(sa + 16384 + off, W + (size_t)(n0 + row) * 1024 + s * 32 + ch * 4);
        }
        CP_COMMIT();
    };

    stage_load(0, 0);
    stage_load(1, 1);

    for (int s = 0; s < 32; s++) {
        const int buf = s & 1;
        if (s >= 30) { CP_WAIT0(); } else { CP_WAIT1(); }
        __syncthreads();

        const uint32_t As_a = sbase + buf * 32768;
        const uint32_t Bs_a = As_a + 16384;

#pragma unroll
        for (int kc = 0; kc < 2; kc++) {
            uint32_t bhf[2][4], bmf[2][4];
#pragma unroll
            for (int ng = 0; ng < 2; ng++) {
                int row = wn * 32 + ng * 16 + ((lid >> 4) << 3) + (lid & 7);
                int ch  = 2 * kc + ((lid >> 3) & 1);
                uint32_t rb = Bs_a + row * 128;
                LDSM_X4(bhf[ng][0], bhf[ng][1], bhf[ng][2], bhf[ng][3],
                        rb + ((ch ^ (row & 7)) << 4));
                LDSM_X4(bmf[ng][0], bmf[ng][1], bmf[ng][2], bmf[ng][3],
                        rb + (((ch + 4) ^ (row & 7)) << 4));
            }
#pragma unroll
            for (int mi = 0; mi < 4; mi++) {
                int row = wm * 64 + mi * 16 + (lid & 15);
                int ch  = 2 * kc + (lid >> 4);
                uint32_t ra = As_a + row * 128;
                uint32_t ah[4], am[4];
                LDSM_X4(ah[0], ah[1], ah[2], ah[3], ra + ((ch ^ (row & 7)) << 4));
                LDSM_X4(am[0], am[1], am[2], am[3], ra + (((ch + 4) ^ (row & 7)) << 4));
#pragma unroll
                for (int ng = 0; ng < 2; ng++) {
                    MMA_BF16(c[mi][2 * ng],     am, bhf[ng][0], bhf[ng][1]);
                    MMA_BF16(c[mi][2 * ng],     ah, bmf[ng][0], bmf[ng][1]);
                    MMA_BF16(c[mi][2 * ng],     ah, bhf[ng][0], bhf[ng][1]);
                    MMA_BF16(c[mi][2 * ng + 1], am, bhf[ng][2], bhf[ng][3]);
                    MMA_BF16(c[mi][2 * ng + 1], ah, bmf[ng][2], bmf[ng][3]);
                    MMA_BF16(c[mi][2 * ng + 1], ah, bhf[ng][2], bhf[ng][3]);
                }
            }
        }

        __syncthreads();
        if (s < 30) stage_load(buf, s + 2);
    }

    // ---------------- epilogue ----------------
    const int rbase = m0 + wm * 64 + (lid >> 2);
    const int cbase = n0 + wn * 32 + (lid & 3) * 2;
    const float neg_lt = -logf(10000.0f) / 64.0f;

    if (mode == 3) {
#pragma unroll
        for (int mi = 0; mi < 4; mi++) {
#pragma unroll
            for (int nj = 0; nj < 4; nj++) {
                int row0 = rbase + mi * 16;
                int col  = cbase + nj * 8;
                *(float2*)(outp + (size_t)row0 * DMODEL + col) =
                    make_float2(c[mi][nj][0], c[mi][nj][1]);
                *(float2*)(outp + (size_t)(row0 + 8) * DMODEL + col) =
                    make_float2(c[mi][nj][2], c[mi][nj][3]);
            }
        }
    } else if (mode == 2) {
#pragma unroll
        for (int mi = 0; mi < 4; mi++) {
#pragma unroll
            for (int half = 0; half < 2; half++) {
                int row  = rbase + mi * 16 + half * 8;
                int b    = row >> 11;
                int srow = row & (S_LEN - 1);
#pragma unroll
                for (int nj = 0; nj < 4; nj++) {
                    int col = cbase + nj * 8;
                    int h   = col >> 6;
                    int d   = col & 63;
                    *(float2*)(g_V + (((size_t)(b * NHEADS + h) * S_LEN + srow) * DK) + d) =
                        make_float2(c[mi][nj][half * 2], c[mi][nj][half * 2 + 1]);
                }
            }
        }
    } else {
        uint32_t* basep = (mode == 0) ? g_Qs : g_Ks;
#pragma unroll
        for (int mi = 0; mi < 4; mi++) {
#pragma unroll
            for (int half = 0; half < 2; half++) {
                int row  = rbase + mi * 16 + half * 8;
                int b    = row >> 11;
                int srow = row & (S_LEN - 1);
                float p  = (float)pos[srow];
#pragma unroll
                for (int nj = 0; nj < 4; nj++) {
                    int col = cbase + nj * 8;
                    int h   = col >> 6;
                    int d   = col & 63;
                    float x1 = c[mi][nj][half * 2];
                    float x2 = c[mi][nj][half * 2 + 1];
                    float fr = expf((float)d * neg_lt);
                    float sn, cs;
                    sincosf(p * fr, &sn, &cs);
                    float r1 = x1 * cs - x2 * sn;
                    float r2 = x1 * sn + x2 * cs;
                    uint32_t hi, mid;
                    bf16_split2(r1, r2, hi, mid);
                    uint32_t* dst = basep +
                        ((size_t)(b * NHEADS + h) * S_LEN + srow) * 64;
                    dst[d >> 1]        = hi;
                    dst[32 + (d >> 1)] = mid;
                }
            }
        }
    }
}

// ===========================================================================
// 3xBF16 tensor-core flash attention (causal).
// CTA: 128 q-rows of one (b,h). 8 warps x 16 q-rows, kv tiles of 64.
// Smem: Q 32KB, P 32KB, K double buf 2x16KB, Vt 16KB. Rows of 256B
// ([hi 128B | mid 128B], 16B chunks swizzled within each 8-chunk group).
// ===========================================================================
__global__ __launch_bounds__(256) void attn_mma_kernel()
{
    extern __shared__ char dynsmem[];

    const int t   = threadIdx.x;
    const int wid = t >> 5;
    const int lid = t & 31;
    const int q0  = blockIdx.x * 128;
    const int bh  = blockIdx.y;
    const int b   = bh >> 4;
    const int h   = bh & 15;

    const uint32_t* __restrict__ Qg = g_Qs + (size_t)bh * S_LEN * 64;
    const uint32_t* __restrict__ Kg = g_Ks + (size_t)bh * S_LEN * 64;
    const float*    __restrict__ Vp = g_V  + (size_t)bh * S_LEN * DK;

    uint32_t raw = smem_u32(dynsmem);
    uint32_t pad = (1024u - (raw & 1023u)) & 1023u;
    char*    sp  = dynsmem + pad;
    const uint32_t sQ  = raw + pad;
    const uint32_t sP  = sQ + 32768;
    const uint32_t sK0 = sQ + 65536;
    const uint32_t sK1 = sQ + 81920;
    const uint32_t sV  = sQ + 98304;
    char* spP = sp + 32768;
    char* spV = sp + 98304;

    // Q tile (cp.async from split array)
#pragma unroll
    for (int i = 0; i < 8; i++) {
        int idx = i * 256 + t, row = idx >> 4, ch = idx & 15;
        uint32_t dst = sQ + row * 256 + (ch & 8) * 16 +
                       (((ch & 7) ^ (row & 7)) << 4);
        cp_async16(dst, Qg + (size_t)(q0 + row) * 64 + ch * 4);
    }
    // K tile 0
#pragma unroll
    for (int i = 0; i < 4; i++) {
        int idx = i * 256 + t, row = idx >> 4, ch = idx & 15;
        uint32_t dst = sK0 + row * 256 + (ch & 8) * 16 +
                       (((ch & 7) ^ (row & 7)) << 4);
        cp_async16(dst, Kg + (size_t)row * 64 + ch * 4);
    }
    CP_COMMIT();

    // V tile 0 (f32, to regs)
    float4 vreg[4];
#pragma unroll
    for (int i = 0; i < 4; i++) {
        int idx = i * 256 + t, row = idx >> 4, ch = idx & 15;
        vreg[i] = *(const float4*)(Vp + (size_t)row * DK + ch * 4);
    }
    CP_WAIT0();
    __syncthreads();

    float o[8][4];
#pragma unroll
    for (int i = 0; i < 8; i++)
#pragma unroll
        for (int j = 0; j < 4; j++) o[i][j] = 0.f;
    float mrow[2] = {-1e30f, -1e30f};
    float lrow[2] = {0.f, 0.f};

    const int ntiles = (q0 >> 6) + 2;

    for (int kt = 0; kt < ntiles; kt++) {
        // ---- store V transposed + split into sVt ----
#pragma unroll
        for (int i = 0; i < 4; i++) {
            int idx = i * 256 + t, kv = idx >> 4, ch = idx & 15;
            int d0 = ch * 4;
            float vals[4] = {vreg[i].x, vreg[i].y, vreg[i].z, vreg[i].w};
#pragma unroll
            for (int j = 0; j < 4; j++) {
                int d = d0 + j;
                __nv_bfloat16 hb = __float2bfloat16(vals[j]);
                float hf = __bfloat162float(hb);
                __nv_bfloat16 mb = __float2bfloat16(vals[j] - hf);
                uint32_t off = d * 256 + (((kv >> 3) ^ (d & 7)) << 4) + (kv & 7) * 2;
                *(__nv_bfloat16*)(spV + off)       = hb;
                *(__nv_bfloat16*)(spV + off + 128) = mb;
            }
        }
        __syncthreads();

        const uint32_t sKc = (kt & 1) ? sK1 : sK0;

        // prefetch next K (cp.async) and V (regs)
        if (kt + 1 < ntiles) {
            const int k0n = (kt + 1) * 64;
            const uint32_t sKn = (kt & 1) ? sK0 : sK1;
#pragma unroll
            for (int i = 0; i < 4; i++) {
                int idx = i * 256 + t, row = idx >> 4, ch = idx & 15;
                uint32_t dst = sKn + row * 256 + (ch & 8) * 16 +
                               (((ch & 7) ^ (row & 7)) << 4);
                cp_async16(dst, Kg + (size_t)(k0n + row) * 64 + ch * 4);
            }
            CP_COMMIT();
#pragma unroll
            for (int i = 0; i < 4; i++) {
                int idx = i * 256 + t, row = idx >> 4, ch = idx & 15;
                vreg[i] = *(const float4*)(Vp + (size_t)(k0n + row) * DK + ch * 4);
            }
        }

        // ---- S = Q K^T (3xBF16) ----
        float s[8][4];
#pragma unroll
        for (int i = 0; i < 8; i++)
#pragma unroll
            for (int j = 0; j < 4; j++) s[i][j] = 0.f;

#pragma unroll
        for (int kc = 0; kc < 4; kc++) {
            int rowa = 16 * wid + (lid & 15);
            int cha  = 2 * kc + (lid >> 4);
            uint32_t ra = sQ + rowa * 256;
            uint32_t ah[4], am[4];
            LDSM_X4(ah[0], ah[1], ah[2], ah[3],
                    ra + ((cha ^ (rowa & 7)) << 4));
            LDSM_X4(am[0], am[1], am[2], am[3],
                    ra + 128 + ((cha ^ (rowa & 7)) << 4));
#pragma unroll
            for (int ng = 0; ng < 4; ng++) {
                int rowb = ng * 16 + ((lid >> 4) << 3) + (lid & 7);
                int chb  = 2 * kc + ((lid >> 3) & 1);
                uint32_t rb = sKc + rowb * 256;
                uint32_t bhf[4], bmf[4];
                LDSM_X4(bhf[0], bhf[1], bhf[2], bhf[3],
                        rb + ((chb ^ (rowb & 7)) << 4));
                LDSM_X4(bmf[0], bmf[1], bmf[2], bmf[3],
                        rb + 128 + ((chb ^ (rowb & 7)) << 4));
                MMA_BF16(s[2 * ng],     am, bhf[0], bhf[1]);
                MMA_BF16(s[2 * ng],     ah, bmf[0], bmf[1]);
                MMA_BF16(s[2 * ng],     ah, bhf[0], bhf[1]);
                MMA_BF16(s[2 * ng + 1], am, bhf[2], bhf[3]);
                MMA_BF16(s[2 * ng + 1], ah, bmf[2], bmf[3]);
                MMA_BF16(s[2 * ng + 1], ah, bhf[2], bhf[3]);
            }
        }

        // ---- scale + causal mask ----
        const int k0 = kt * 64;
        const int qA = q0 + 16 * wid + (lid >> 2);
#pragma unroll
        for (int nf = 0; nf < 8; nf++) {
            int colb = k0 + nf * 8 + 2 * (lid & 3);
#pragma unroll
            for (int e = 0; e < 4; e++) {
                int q  = qA + ((e >> 1) << 3);
                int kv = colb + (e & 1);
                float v = s[nf][e] * 0.125f;
                s[nf][e] = (kv > q) ? -1e30f : v;
            }
        }

        // ---- online softmax ----
#pragma unroll
        for (int half = 0; half < 2; half++) {
            float ml = -1e30f;
#pragma unroll
            for (int nf = 0; nf < 8; nf++)
                ml = fmaxf(ml, fmaxf(s[nf][2 * half], s[nf][2 * half + 1]));
            ml = fmaxf(ml, __shfl_xor_sync(0xffffffffu, ml, 1));
            ml = fmaxf(ml, __shfl_xor_sync(0xffffffffu, ml, 2));
            float mn = fmaxf(mrow[half], ml);
            float al = __expf(mrow[half] - mn);
            mrow[half] = mn;
            float ls = 0.f;
#pragma unroll
            for (int nf = 0; nf < 8; nf++) {
                float e0 = __expf(s[nf][2 * half] - mn);
                float e1 = __expf(s[nf][2 * half + 1] - mn);
                s[nf][2 * half] = e0;
                s[nf][2 * half + 1] = e1;
                ls += e0 + e1;
            }
            ls += __shfl_xor_sync(0xffffffffu, ls, 1);
            ls += __shfl_xor_sync(0xffffffffu, ls, 2);
            lrow[half] = lrow[half] * al + ls;
#pragma unroll
            for (int nf = 0; nf < 8; nf++) {
                o[nf][2 * half] *= al;
                o[nf][2 * half + 1] *= al;
            }
        }

        // ---- store P (split, own 16 rows) ----
        {
            int pr0 = 16 * wid + (lid >> 2), pr1 = pr0 + 8;
#pragma unroll
            for (int nf = 0; nf < 8; nf++) {
                uint32_t hi, mid;
                bf16_split2(s[nf][0], s[nf][1], hi, mid);
                uint32_t off0 = pr0 * 256 + ((nf ^ (pr0 & 7)) << 4) + (lid & 3) * 4;
                *(uint32_t*)(spP + off0)       = hi;
                *(uint32_t*)(spP + off0 + 128) = mid;
                bf16_split2(s[nf][2], s[nf][3], hi, mid);
                uint32_t off1 = pr1 * 256 + ((nf ^ (pr1 & 7)) << 4) + (lid & 3) * 4;
                *(uint32_t*)(spP + off1)       = hi;
                *(uint32_t*)(spP + off1 + 128) = mid;
            }
        }
        __syncwarp();

        // ---- O += P V (3xBF16) ----
#pragma unroll
        for (int kc = 0; kc < 4; kc++) {
            int rowa = 16 * wid + (lid & 15);
            int cha  = 2 * kc + (lid >> 4);
            uint32_t ra = sP + rowa * 256;
            uint32_t ah[4], am[4];
            LDSM_X4(ah[0], ah[1], ah[2], ah[3],
                    ra + ((cha ^ (rowa & 7)) << 4));
            LDSM_X4(am[0], am[1], am[2], am[3],
                    ra + 128 + ((cha ^ (rowa & 7)) << 4));
#pragma unroll
            for (int ng = 0; ng < 4; ng++) {
                int rowb = ng * 16 + ((lid >> 4) << 3) + (lid & 7);
                int chb  = 2 * kc + ((lid >> 3) & 1);
                uint32_t rb = sV + rowb * 256;
                uint32_t bhf[4], bmf[4];
                LDSM_X4(bhf[0], bhf[1], bhf[2], bhf[3],
                        rb + ((chb ^ (rowb & 7)) << 4));
                LDSM_X4(bmf[0], bmf[1], bmf[2], bmf[3],
                        rb + 128 + ((chb ^ (rowb & 7)) << 4));
                MMA_BF16(o[2 * ng],     am, bhf[0], bhf[1]);
                MMA_BF16(o[2 * ng],     ah, bmf[0], bmf[1]);
                MMA_BF16(o[2 * ng],     ah, bhf[0], bhf[1]);
                MMA_BF16(o[2 * ng + 1], am, bhf[2], bhf[3]);
                MMA_BF16(o[2 * ng + 1], ah, bmf[2], bmf[3]);
                MMA_BF16(o[2 * ng + 1], ah, bhf[2], bhf[3]);
            }
        }

        if (kt + 1 < ntiles) CP_WAIT0();
        __syncthreads();
    }

    // ---- normalize + write split rows into g_Os ----
    const float i0 = 1.0f / lrow[0];
    const float i1 = 1.0f / lrow[1];
    const int qA = q0 + 16 * wid + (lid >> 2);
    const size_t row0 = (size_t)(b * S_LEN + qA) * 1024;
    const size_t row1 = (size_t)(b * S_LEN + qA + 8) * 1024;
#pragma unroll
    for (int nf = 0; nf < 8; nf++) {
        int col = h * 64 + nf * 8 + 2 * (lid & 3);
        int kb = col >> 5;
        int jj = (col & 31) >> 1;
        uint32_t hi, mid;
        bf16_split2(o[nf][0] * i0, o[nf][1] * i0, hi, mid);
        g_Os[row0 + kb * 32 + jj]      = hi;
        g_Os[row0 + kb * 32 + 16 + jj] = mid;
        bf16_split2(o[nf][2] * i1, o[nf][3] * i1, hi, mid);
        g_Os[row1 + kb * 32 + jj]      = hi;
        g_Os[row1 + kb * 32 + 16 + jj] = mid;
    }
}

// ---------------------------------------------------------------------------
extern "C" void kernel_launch(void* const* d_in, const int* in_sizes, int n_in,
                              void* d_out, int out_size)
{
    const float* x   = (const float*)d_in[0];
    const int*   pos = (const int*)  d_in[1];
    const float* Wq  = (const float*)d_in[2];
    const float* Wk  = (const float*)d_in[3];
    const float* Wv  = (const float*)d_in[4];
    const float* Wo  = (const float*)d_in[5];
    float* out = (float*)d_out;

    const int DYN_GEMM = 2 * 32768 + 1024;
    const int DYN_ATTN = 114688 + 1024;
    cudaFuncSetAttribute(mma_gemm_kernel,
                         cudaFuncAttributeMaxDynamicSharedMemorySize, DYN_GEMM);
    cudaFuncSetAttribute(attn_mma_kernel,
                         cudaFuncAttributeMaxDynamicSharedMemorySize, DYN_ATTN);

    // Split preps
    split_kernel<<<(MROWS * 256) / 256, 256>>>(x, 0, MROWS * 256);
    split_kernel<<<(DMODEL * 256) / 256, 256>>>(Wq, 1, DMODEL * 256);
    split_kernel<<<(DMODEL * 256) / 256, 256>>>(Wk, 2, DMODEL * 256);
    split_kernel<<<(DMODEL * 256) / 256, 256>>>(Wv, 3, DMODEL * 256);
    split_kernel<<<(DMODEL * 256) / 256, 256>>>(Wo, 4, DMODEL * 256);

    // QKV projections + RoPE (3xBF16)
    mma_gemm_kernel<<<dim3(DMODEL / 128, MROWS / 128, 3), 256, DYN_GEMM>>>(
        pos, nullptr, -1);
    // Causal flash attention (3xBF16)
    attn_mma_kernel<<<dim3(S_LEN / 128, BATCH * NHEADS), 256, DYN_ATTN>>>();
    // Output projection (3xBF16)
    mma_gemm_kernel<<<dim3(DMODEL / 128, MROWS / 128, 1), 256, DYN_GEMM>>>(
        pos, out, 3);
}

// round 8
// speedup vs baseline: 3.6152x; 1.1765x over previous
#include <cuda_runtime.h>
#include <cuda_bf16.h>
#include <math.h>
#include <stdint.h>

#define S_LEN  2048
#define DMODEL 1024
#define NHEADS 16
#define DK     64
#define BATCH  2
#define MROWS  (BATCH * S_LEN)   // 4096

// qk scale 1/8 folded with log2(e) into Q, so softmax uses exp2
#define QSCALE 0.18033688011112042f   // 0.125 * log2(e)

// ---------------------------------------------------------------------------
// Device-global scratch. Split layout per 32-col block: [16 u32 hi | 16 u32 mid]
// (bf16x2 per u32, pair = adjacent columns)
// ---------------------------------------------------------------------------
__device__ uint32_t g_Xs[MROWS * DMODEL];              // x split
__device__ uint32_t g_Ws[4][DMODEL * DMODEL];          // Wq,Wk,Wv,Wo split
__device__ uint32_t g_Qs[BATCH * NHEADS * S_LEN * 64]; // Q split (row: 32 hi|32 mid)
__device__ uint32_t g_Ks[BATCH * NHEADS * S_LEN * 64]; // K split
__device__ float    g_V [BATCH * NHEADS * S_LEN * DK]; // V fp32 (b,h,s,d)
__device__ uint32_t g_Vts[BATCH * NHEADS * DK * (S_LEN / 2) * 2]; // V^T split (b,h,d,s)
__device__ uint32_t g_Os[MROWS * DMODEL];              // attention out, split

// ===========================================================================
// PTX helpers
// ===========================================================================
__device__ __forceinline__ uint32_t smem_u32(const void* p) {
    uint32_t a;
    asm("{ .reg .u64 t; cvta.to.shared.u64 t, %1; cvt.u32.u64 %0, t; }"
        : "=r"(a) : "l"(p));
    return a;
}
__device__ __forceinline__ void cp_async16(uint32_t dst, const void* src) {
    asm volatile("cp.async.cg.shared.global [%0], [%1], 16;"
                 :: "r"(dst), "l"(src));
}
#define CP_COMMIT() asm volatile("cp.async.commit_group;" ::: "memory")
#define CP_WAIT1()  asm volatile("cp.async.wait_group 1;" ::: "memory")
#define CP_WAIT0()  asm volatile("cp.async.wait_group 0;" ::: "memory")

#define LDSM_X4(r0, r1, r2, r3, addr)                                     \
    asm volatile("ldmatrix.sync.aligned.m8n8.x4.shared.b16 "              \
                 "{%0,%1,%2,%3}, [%4];"                                   \
                 : "=r"(r0), "=r"(r1), "=r"(r2), "=r"(r3) : "r"(addr))

#define MMA_BF16(c, a, b0, b1)                                            \
    asm volatile("mma.sync.aligned.m16n8k16.row.col.f32.bf16.bf16.f32 "   \
                 "{%0,%1,%2,%3},{%4,%5,%6,%7},{%8,%9},{%0,%1,%2,%3};"     \
                 : "+f"((c)[0]), "+f"((c)[1]), "+f"((c)[2]), "+f"((c)[3]) \
                 : "r"((a)[0]), "r"((a)[1]), "r"((a)[2]), "r"((a)[3]),    \
                   "r"(b0), "r"(b1))

__device__ __forceinline__ void bf16_split2(float x0, float x1,
                                            uint32_t& hi2, uint32_t& mid2) {
    uint32_t h;
    asm("cvt.rn.bf16x2.f32 %0, %2, %1;" : "=r"(h) : "f"(x0), "f"(x1));
    float h0 = __uint_as_float(h << 16);
    float h1 = __uint_as_float(h & 0xffff0000u);
    float m0 = x0 - h0, m1 = x1 - h1;
    uint32_t m;
    asm("cvt.rn.bf16x2.f32 %0, %2, %1;" : "=r"(m) : "f"(m0), "f"(m1));
    hi2 = h; mid2 = m;
}

// ===========================================================================
// Split prep: f32 row-major [rows][1024] -> split u32 [rows][1024]
// ===========================================================================
__global__ __launch_bounds__(256) void split_kernel(const float* __restrict__ in,
                                                    int which, int n4) {
    int idx = blockIdx.x * 256 + threadIdx.x;
    if (idx >= n4) return;
    uint32_t* out = (which == 0) ? g_Xs : g_Ws[which - 1];
    int r  = idx >> 8;
    int p4 = idx & 255;
    int kb = p4 >> 3, q = p4 & 7;
    float4 v = *(const float4*)(in + (size_t)idx * 4);
    uint32_t h0, m0, h1, m1;
    bf16_split2(v.x, v.y, h0, m0);
    bf16_split2(v.z, v.w, h1, m1);
    uint32_t* o = out + (size_t)r * 1024 + kb * 32;
    *(uint2*)(o + 2 * q)      = make_uint2(h0, h1);
    *(uint2*)(o + 16 + 2 * q) = make_uint2(m0, m1);
}

// ===========================================================================
// V transpose + split: g_V (b,h,s,d) f32 -> g_Vts (b,h,d,s) split
// ===========================================================================
__global__ __launch_bounds__(256) void vts_kernel() {
    __shared__ float sT[64 * 65];
    const int t  = threadIdx.x;
    const int s0 = blockIdx.x * 64;
    const int bh = blockIdx.y;
    const float* __restrict__ Vp = g_V + (size_t)bh * S_LEN * DK;

#pragma unroll
    for (int i = 0; i < 4; i++) {
        int idx = i * 256 + t, s = idx >> 4, ch = idx & 15;
        float4 v = *(const float4*)(Vp + (size_t)(s0 + s) * DK + ch * 4);
        sT[(ch * 4 + 0) * 65 + s] = v.x;
        sT[(ch * 4 + 1) * 65 + s] = v.y;
        sT[(ch * 4 + 2) * 65 + s] = v.z;
        sT[(ch * 4 + 3) * 65 + s] = v.w;
    }
    __syncthreads();

    const int d = t >> 2;
    const int q = t & 3;
    uint32_t* dst = g_Vts + (size_t)bh * 64 * 2048 + (size_t)d * 2048 +
                    ((s0 >> 5) + (q >> 1)) * 32;
    uint32_t hi[8], mid[8];
#pragma unroll
    for (int p = 0; p < 8; p++) {
        int sl = q * 16 + 2 * p;
        bf16_split2(sT[d * 65 + sl], sT[d * 65 + sl + 1], hi[p], mid[p]);
    }
    const int off = (q & 1) * 8;
#pragma unroll
    for (int p = 0; p < 8; p += 4) {
        *(uint4*)(dst + off + p)      = make_uint4(hi[p], hi[p+1], hi[p+2], hi[p+3]);
        *(uint4*)(dst + 16 + off + p) = make_uint4(mid[p], mid[p+1], mid[p+2], mid[p+3]);
    }
}

// ===========================================================================
// 3xBF16 GEMM, 3-stage cp.async ring, one barrier per stage.
// mode 0=Q (RoPE*scale + split bhsd), 1=K (RoPE + split bhsd),
// 2=V (f32 bhsd), 3=O-proj (f32 row-major out)
// ===========================================================================
__global__ __launch_bounds__(256) void mma_gemm_kernel(
    const int* __restrict__ pos,
    float*     __restrict__ outp,
    int mode_sel)
{
    extern __shared__ char dynsmem[];

    const int mode = (mode_sel < 0) ? (int)blockIdx.z : mode_sel;
    const uint32_t* __restrict__ A = (mode == 3) ? g_Os : g_Xs;
    const uint32_t* __restrict__ W = g_Ws[mode];

    const int t   = threadIdx.x;
    const int wid = t >> 5;
    const int lid = t & 31;
    const int wm  = wid >> 2;
    const int wn  = wid & 3;
    const int n0  = blockIdx.x * 128;
    const int m0  = blockIdx.y * 128;

    uint32_t raw = smem_u32(dynsmem);
    uint32_t pad = (1024u - (raw & 1023u)) & 1023u;
    const uint32_t sbase = raw + pad;

    float c[4][4][4];
#pragma unroll
    for (int i = 0; i < 4; i++)
#pragma unroll
        for (int j = 0; j < 4; j++)
#pragma unroll
            for (int k = 0; k < 4; k++) c[i][j][k] = 0.f;

    auto stage_load = [&](int buf, int s) {
        const uint32_t sa = sbase + buf * 32768;
#pragma unroll
        for (int i = 0; i < 4; i++) {
            int idx = i * 256 + t;
            int row = idx >> 3;
            int ch  = idx & 7;
            uint32_t off = (uint32_t)(row * 128 + ((ch ^ (row & 7)) << 4));
            cp_async16(sa + off,         A + (size_t)(m0 + row) * 1024 + s * 32 + ch * 4);
            cp_async16(sa + 16384 + off, W + (size_t)(n0 + row) * 1024 + s * 32 + ch * 4);
        }
        CP_COMMIT();
    };

    stage_load(0, 0);
    stage_load(1, 1);

    int buf = 0;
    for (int s = 0; s < 32; s++) {
        if (s == 31) { CP_WAIT0(); } else { CP_WAIT1(); }
        __syncthreads();
        if (s + 2 < 32) {
            int nb = buf + 2; if (nb >= 3) nb -= 3;
            stage_load(nb, s + 2);
        }

        const uint32_t As_a = sbase + buf * 32768;
        const uint32_t Bs_a = As_a + 16384;

#pragma unroll
        for (int kc = 0; kc < 2; kc++) {
            uint32_t bhf[2][4], bmf[2][4];
#pragma unroll
            for (int ng = 0; ng < 2; ng++) {
                int row = wn * 32 + ng * 16 + ((lid >> 4) << 3) + (lid & 7);
                int ch  = 2 * kc + ((lid >> 3) & 1);
                uint32_t rb = Bs_a + row * 128;
                LDSM_X4(bhf[ng][0], bhf[ng][1], bhf[ng][2], bhf[ng][3],
                        rb + ((ch ^ (row & 7)) << 4));
                LDSM_X4(bmf[ng][0], bmf[ng][1], bmf[ng][2], bmf[ng][3],
                        rb + (((ch + 4) ^ (row & 7)) << 4));
            }
#pragma unroll
            for (int mi = 0; mi < 4; mi++) {
                int row = wm * 64 + mi * 16 + (lid & 15);
                int ch  = 2 * kc + (lid >> 4);
                uint32_t ra = As_a + row * 128;
                uint32_t ah[4], am[4];
                LDSM_X4(ah[0], ah[1], ah[2], ah[3], ra + ((ch ^ (row & 7)) << 4));
                LDSM_X4(am[0], am[1], am[2], am[3], ra + (((ch + 4) ^ (row & 7)) << 4));
#pragma unroll
                for (int ng = 0; ng < 2; ng++) {
                    MMA_BF16(c[mi][2 * ng],     am, bhf[ng][0], bhf[ng][1]);
                    MMA_BF16(c[mi][2 * ng],     ah, bmf[ng][0], bmf[ng][1]);
                    MMA_BF16(c[mi][2 * ng],     ah, bhf[ng][0], bhf[ng][1]);
                    MMA_BF16(c[mi][2 * ng + 1], am, bhf[ng][2], bhf[ng][3]);
                    MMA_BF16(c[mi][2 * ng + 1], ah, bmf[ng][2], bmf[ng][3]);
                    MMA_BF16(c[mi][2 * ng + 1], ah, bhf[ng][2], bhf[ng][3]);
                }
            }
        }
        buf++; if (buf >= 3) buf -= 3;
    }

    // ---------------- epilogue ----------------
    const int rbase = m0 + wm * 64 + (lid >> 2);
    const int cbase = n0 + wn * 32 + (lid & 3) * 2;
    const float neg_lt = -logf(10000.0f) / 64.0f;

    if (mode == 3) {
#pragma unroll
        for (int mi = 0; mi < 4; mi++) {
#pragma unroll
            for (int nj = 0; nj < 4; nj++) {
                int row0 = rbase + mi * 16;
                int col  = cbase + nj * 8;
                *(float2*)(outp + (size_t)row0 * DMODEL + col) =
                    make_float2(c[mi][nj][0], c[mi][nj][1]);
                *(float2*)(outp + (size_t)(row0 + 8) * DMODEL + col) =
                    make_float2(c[mi][nj][2], c[mi][nj][3]);
            }
        }
    } else if (mode == 2) {
#pragma unroll
        for (int mi = 0; mi < 4; mi++) {
#pragma unroll
            for (int half = 0; half < 2; half++) {
                int row  = rbase + mi * 16 + half * 8;
                int b    = row >> 11;
                int srow = row & (S_LEN - 1);
#pragma unroll
                for (int nj = 0; nj < 4; nj++) {
                    int col = cbase + nj * 8;
                    int h   = col >> 6;
                    int d   = col & 63;
                    *(float2*)(g_V + (((size_t)(b * NHEADS + h) * S_LEN + srow) * DK) + d) =
                        make_float2(c[mi][nj][half * 2], c[mi][nj][half * 2 + 1]);
                }
            }
        }
    } else {
        uint32_t* basep = (mode == 0) ? g_Qs : g_Ks;
        const float osc = (mode == 0) ? QSCALE : 1.0f;
#pragma unroll
        for (int mi = 0; mi < 4; mi++) {
#pragma unroll
            for (int half = 0; half < 2; half++) {
                int row  = rbase + mi * 16 + half * 8;
                int b    = row >> 11;
                int srow = row & (S_LEN - 1);
                float p  = (float)pos[srow];
#pragma unroll
                for (int nj = 0; nj < 4; nj++) {
                    int col = cbase + nj * 8;
                    int h   = col >> 6;
                    int d   = col & 63;
                    float x1 = c[mi][nj][half * 2];
                    float x2 = c[mi][nj][half * 2 + 1];
                    float fr = expf((float)d * neg_lt);
                    float sn, cs;
                    sincosf(p * fr, &sn, &cs);
                    float r1 = (x1 * cs - x2 * sn) * osc;
                    float r2 = (x1 * sn + x2 * cs) * osc;
                    uint32_t hi, mid;
                    bf16_split2(r1, r2, hi, mid);
                    uint32_t* dst = basep +
                        ((size_t)(b * NHEADS + h) * S_LEN + srow) * 64;
                    dst[d >> 1]        = hi;
                    dst[32 + (d >> 1)] = mid;
                }
            }
        }
    }
}

// ===========================================================================
// 3xBF16 flash attention (causal). CTA: 128 q-rows of one (b,h); 8 warps.
// ===========================================================================
__global__ __launch_bounds__(256) void attn_mma_kernel()
{
    extern __shared__ char dynsmem[];

    const int t   = threadIdx.x;
    const int wid = t >> 5;
    const int lid = t & 31;
    const int q0  = blockIdx.x * 128;
    const int bh  = blockIdx.y;
    const int b   = bh >> 4;
    const int h   = bh & 15;

    const uint32_t* __restrict__ Qg  = g_Qs  + (size_t)bh * S_LEN * 64;
    const uint32_t* __restrict__ Kg  = g_Ks  + (size_t)bh * S_LEN * 64;
    const uint32_t* __restrict__ Vtg = g_Vts + (size_t)bh * 64 * 2048;

    uint32_t raw = smem_u32(dynsmem);
    uint32_t pad = (1024u - (raw & 1023u)) & 1023u;
    char*    sp  = dynsmem + pad;
    const uint32_t sQ  = raw + pad;
    const uint32_t sP  = sQ + 32768;
    const uint32_t sK0 = sQ + 65536;
    const uint32_t sK1 = sQ + 81920;
    const uint32_t sV  = sQ + 98304;
    char* spP = sp + 32768;
    char* spV = sp + 98304;

    // Q tile + K tile 0 via cp.async (one group)
#pragma unroll
    for (int i = 0; i < 8; i++) {
        int idx = i * 256 + t, row = idx >> 4, ch = idx & 15;
        uint32_t dst = sQ + row * 256 + (ch & 8) * 16 +
                       (((ch & 7) ^ (row & 7)) << 4);
        cp_async16(dst, Qg + (size_t)(q0 + row) * 64 + ch * 4);
    }
#pragma unroll
    for (int i = 0; i < 4; i++) {
        int idx = i * 256 + t, row = idx >> 4, ch = idx & 15;
        uint32_t dst = sK0 + row * 256 + (ch & 8) * 16 +
                       (((ch & 7) ^ (row & 7)) << 4);
        cp_async16(dst, Kg + (size_t)row * 64 + ch * 4);
    }
    CP_COMMIT();

    // V tile 0 (pre-split, transposed) -> regs
    uint4 vreg[4];
#pragma unroll
    for (int i = 0; i < 4; i++) {
        int idx = i * 256 + t, d = idx >> 4, ch = idx & 15;
        vreg[i] = *(const uint4*)(Vtg + (size_t)d * 2048 + ch * 4);
    }
    CP_WAIT0();
    __syncthreads();

    float o[8][4];
#pragma unroll
    for (int i = 0; i < 8; i++)
#pragma unroll
        for (int j = 0; j < 4; j++) o[i][j] = 0.f;
    float mrow[2] = {-1e30f, -1e30f};
    float lrow[2] = {0.f, 0.f};

    const int ntiles = (q0 >> 6) + 2;
    const int wq_min = q0 + 16 * wid;       // warp's first q row
    const int wq_max = wq_min + 15;         // warp's last q row

    for (int kt = 0; kt < ntiles; kt++) {
        const int k0 = kt * 64;
        const bool active = (k0 <= wq_max);

        // ---- store V tile (chunk remap: [h0 m0 h1 m1] -> [h0 h1 m0 m1]) ----
#pragma unroll
        for (int i = 0; i < 4; i++) {
            int idx = i * 256 + t, d = idx >> 4, chs = idx & 15;
            int g = chs >> 2, bq = chs & 3;
            int chd = (((g << 1) | (g >> 1)) & 3) * 4 + bq;
            *(uint4*)(spV + d * 256 + (chd & 8) * 16 +
                      (((chd & 7) ^ (d & 7)) << 4)) = vreg[i];
        }
        __syncthreads();

        const uint32_t sKc = (kt & 1) ? sK1 : sK0;

        // prefetch next K (cp.async) and next V (regs)
        if (kt + 1 < ntiles) {
            const int k0n = (kt + 1) * 64;
            const uint32_t sKn = (kt & 1) ? sK0 : sK1;
#pragma unroll
            for (int i = 0; i < 4; i++) {
                int idx = i * 256 + t, row = idx >> 4, ch = idx & 15;
                uint32_t dst = sKn + row * 256 + (ch & 8) * 16 +
                               (((ch & 7) ^ (row & 7)) << 4);
                cp_async16(dst, Kg + (size_t)(k0n + row) * 64 + ch * 4);
            }
            CP_COMMIT();
#pragma unroll
            for (int i = 0; i < 4; i++) {
                int idx = i * 256 + t, d = idx >> 4, ch = idx & 15;
                vreg[i] = *(const uint4*)(Vtg + (size_t)d * 2048 +
                                          (kt + 1) * 64 + ch * 4);
            }
        }

        if (active) {
            // ---- S = Q K^T (3xBF16), pre-scaled ----
            float s[8][4];
#pragma unroll
            for (int i = 0; i < 8; i++)
#pragma unroll
                for (int j = 0; j < 4; j++) s[i][j] = 0.f;

#pragma unroll
            for (int kc = 0; kc < 4; kc++) {
                int rowa = 16 * wid + (lid & 15);
                int cha  = 2 * kc + (lid >> 4);
                uint32_t ra = sQ + rowa * 256;
                uint32_t ah[4], am[4];
                LDSM_X4(ah[0], ah[1], ah[2], ah[3],
                        ra + ((cha ^ (rowa & 7)) << 4));
                LDSM_X4(am[0], am[1], am[2], am[3],
                        ra + 128 + ((cha ^ (rowa & 7)) << 4));
#pragma unroll
                for (int ng = 0; ng < 4; ng++) {
                    int rowb = ng * 16 + ((lid >> 4) << 3) + (lid & 7);
                    int chb  = 2 * kc + ((lid >> 3) & 1);
                    uint32_t rb = sKc + rowb * 256;
                    uint32_t bhf[4], bmf[4];
                    LDSM_X4(bhf[0], bhf[1], bhf[2], bhf[3],
                            rb + ((chb ^ (rowb & 7)) << 4));
                    LDSM_X4(bmf[0], bmf[1], bmf[2], bmf[3],
                            rb + 128 + ((chb ^ (rowb & 7)) << 4));
                    MMA_BF16(s[2 * ng],     am, bhf[0], bhf[1]);
                    MMA_BF16(s[2 * ng],     ah, bmf[0], bmf[1]);
                    MMA_BF16(s[2 * ng],     ah, bhf[0], bhf[1]);
                    MMA_BF16(s[2 * ng + 1], am, bhf[2], bhf[3]);
                    MMA_BF16(s[2 * ng + 1], ah, bmf[2], bmf[3]);
                    MMA_BF16(s[2 * ng + 1], ah, bhf[2], bhf[3]);
                }
            }

            // ---- causal mask: needed whenever tile extends past warp's
            //      FIRST q row (k0+63 > wq_min) ----
            const int qA = q0 + 16 * wid + (lid >> 2);
            if (k0 + 63 > wq_min) {
#pragma unroll
                for (int nf = 0; nf < 8; nf++) {
                    int colb = k0 + nf * 8 + 2 * (lid & 3);
#pragma unroll
                    for (int e = 0; e < 4; e++) {
                        int q  = qA + ((e >> 1) << 3);
                        int kv = colb + (e & 1);
                        if (kv > q) s[nf][e] = -1e30f;
                    }
                }
            }

            // ---- online softmax (log2 domain) ----
#pragma unroll
            for (int half = 0; half < 2; half++) {
                float ml = -1e30f;
#pragma unroll
                for (int nf = 0; nf < 8; nf++)
                    ml = fmaxf(ml, fmaxf(s[nf][2 * half], s[nf][2 * half + 1]));
                ml = fmaxf(ml, __shfl_xor_sync(0xffffffffu, ml, 1));
                ml = fmaxf(ml, __shfl_xor_sync(0xffffffffu, ml, 2));
                float mn = fmaxf(mrow[half], ml);
                float al = exp2f(mrow[half] - mn);
                mrow[half] = mn;
                float ls = 0.f;
#pragma unroll
                for (int nf = 0; nf < 8; nf++) {
                    float e0 = exp2f(s[nf][2 * half] - mn);
                    float e1 = exp2f(s[nf][2 * half + 1] - mn);
                    s[nf][2 * half] = e0;
                    s[nf][2 * half + 1] = e1;
                    ls += e0 + e1;
                }
                ls += __shfl_xor_sync(0xffffffffu, ls, 1);
                ls += __shfl_xor_sync(0xffffffffu, ls, 2);
                lrow[half] = lrow[half] * al + ls;
#pragma unroll
                for (int nf = 0; nf < 8; nf++) {
                    o[nf][2 * half] *= al;
                    o[nf][2 * half + 1] *= al;
                }
            }

            // ---- store P (split, own 16 rows) ----
            {
                int pr0 = 16 * wid + (lid >> 2), pr1 = pr0 + 8;
#pragma unroll
                for (int nf = 0; nf < 8; nf++) {
                    uint32_t hi, mid;
                    bf16_split2(s[nf][0], s[nf][1], hi, mid);
                    uint32_t off0 = pr0 * 256 + ((nf ^ (pr0 & 7)) << 4) + (lid & 3) * 4;
                    *(uint32_t*)(spP + off0)       = hi;
                    *(uint32_t*)(spP + off0 + 128) = mid;
                    bf16_split2(s[nf][2], s[nf][3], hi, mid);
                    uint32_t off1 = pr1 * 256 + ((nf ^ (pr1 & 7)) << 4) + (lid & 3) * 4;
                    *(uint32_t*)(spP + off1)       = hi;
                    *(uint32_t*)(spP + off1 + 128) = mid;
                }
            }
            __syncwarp();

            // ---- O += P V (3xBF16) ----
#pragma unroll
            for (int kc = 0; kc < 4; kc++) {
                int rowa = 16 * wid + (lid & 15);
                int cha  = 2 * kc + (lid >> 4);
                uint32_t ra = sP + rowa * 256;
                uint32_t ah[4], am[4];
                LDSM_X4(ah[0], ah[1], ah[2], ah[3],
                        ra + ((cha ^ (rowa & 7)) << 4));
                LDSM_X4(am[0], am[1], am[2], am[3],
                        ra + 128 + ((cha ^ (rowa & 7)) << 4));
#pragma unroll
                for (int ng = 0; ng < 4; ng++) {
                    int rowb = ng * 16 + ((lid >> 4) << 3) + (lid & 7);
                    int chb  = 2 * kc + ((lid >> 3) & 1);
                    uint32_t rb = sV + rowb * 256;
                    uint32_t bhf[4], bmf[4];
                    LDSM_X4(bhf[0], bhf[1], bhf[2], bhf[3],
                            rb + ((chb ^ (rowb & 7)) << 4));
                    LDSM_X4(bmf[0], bmf[1], bmf[2], bmf[3],
                            rb + 128 + ((chb ^ (rowb & 7)) << 4));
                    MMA_BF16(o[2 * ng],     am, bhf[0], bhf[1]);
                    MMA_BF16(o[2 * ng],     ah, bmf[0], bmf[1]);
                    MMA_BF16(o[2 * ng],     ah, bhf[0], bhf[1]);
                    MMA_BF16(o[2 * ng + 1], am, bhf[2], bhf[3]);
                    MMA_BF16(o[2 * ng + 1], ah, bmf[2], bmf[3]);
                    MMA_BF16(o[2 * ng + 1], ah, bhf[2], bhf[3]);
                }
            }
        }

        if (kt + 1 < ntiles) CP_WAIT0();
        __syncthreads();
    }

    // ---- normalize + write split rows into g_Os ----
    const float i0 = 1.0f / lrow[0];
    const float i1 = 1.0f / lrow[1];
    const int qA = q0 + 16 * wid + (lid >> 2);
    const size_t row0 = (size_t)(b * S_LEN + qA) * 1024;
    const size_t row1 = (size_t)(b * S_LEN + qA + 8) * 1024;
#pragma unroll
    for (int nf = 0; nf < 8; nf++) {
        int col = h * 64 + nf * 8 + 2 * (lid & 3);
        int kb = col >> 5;
        int jj = (col & 31) >> 1;
        uint32_t hi, mid;
        bf16_split2(o[nf][0] * i0, o[nf][1] * i0, hi, mid);
        g_Os[row0 + kb * 32 + jj]      = hi;
        g_Os[row0 + kb * 32 + 16 + jj] = mid;
        bf16_split2(o[nf][2] * i1, o[nf][3] * i1, hi, mid);
        g_Os[row1 + kb * 32 + jj]      = hi;
        g_Os[row1 + kb * 32 + 16 + jj] = mid;
    }
}

// ---------------------------------------------------------------------------
extern "C" void kernel_launch(void* const* d_in, const int* in_sizes, int n_in,
                              void* d_out, int out_size)
{
    const float* x   = (const float*)d_in[0];
    const int*   pos = (const int*)  d_in[1];
    const float* Wq  = (const float*)d_in[2];
    const float* Wk  = (const float*)d_in[3];
    const float* Wv  = (const float*)d_in[4];
    const float* Wo  = (const float*)d_in[5];
    float* out = (float*)d_out;

    const int DYN_GEMM = 3 * 32768 + 1024;
    const int DYN_ATTN = 114688 + 1024;
    cudaFuncSetAttribute(mma_gemm_kernel,
                         cudaFuncAttributeMaxDynamicSharedMemorySize, DYN_GEMM);
    cudaFuncSetAttribute(attn_mma_kernel,
                         cudaFuncAttributeMaxDynamicSharedMemorySize, DYN_ATTN);

    // Split preps
    split_kernel<<<(MROWS * 256) / 256, 256>>>(x, 0, MROWS * 256);
    split_kernel<<<(DMODEL * 256) / 256, 256>>>(Wq, 1, DMODEL * 256);
    split_kernel<<<(DMODEL * 256) / 256, 256>>>(Wk, 2, DMODEL * 256);
    split_kernel<<<(DMODEL * 256) / 256, 256>>>(Wv, 3, DMODEL * 256);
    split_kernel<<<(DMODEL * 256) / 256, 256>>>(Wo, 4, DMODEL * 256);

    // QKV projections + RoPE (3xBF16)
    mma_gemm_kernel<<<dim3(DMODEL / 128, MROWS / 128, 3), 256, DYN_GEMM>>>(
        pos, nullptr, -1);
    // V transpose + split for attention
    vts_kernel<<<dim3(S_LEN / 64, BATCH * NHEADS), 256>>>();
    // Causal flash attention (3xBF16)
    attn_mma_kernel<<<dim3(S_LEN / 128, BATCH * NHEADS), 256, DYN_ATTN>>>();
    // Output projection (3xBF16)
    mma_gemm_kernel<<<dim3(DMODEL / 128, MROWS / 128, 1), 256, DYN_GEMM>>>(
        pos, out, 3);
}

// round 10
// speedup vs baseline: 3.7245x; 1.0302x over previous
#include <cuda_runtime.h>
#include <cuda_bf16.h>
#include <math.h>
#include <stdint.h>

#define S_LEN  2048
#define DMODEL 1024
#define NHEADS 16
#define DK     64
#define BATCH  2
#define MROWS  (BATCH * S_LEN)   // 4096

// qk scale 1/8 folded with log2(e) into Q, so softmax uses exp2
#define QSCALE 0.18033688011112042f   // 0.125 * log2(e)

// ---------------------------------------------------------------------------
// Device-global scratch. Split layout per 32-col block: [16 u32 hi | 16 u32 mid]
// (bf16x2 per u32, pair = adjacent columns)
// ---------------------------------------------------------------------------
__device__ uint32_t g_Xs[MROWS * DMODEL];              // x split
__device__ uint32_t g_Ws[4][DMODEL * DMODEL];          // Wq,Wk,Wv,Wo split
__device__ uint32_t g_Qs[BATCH * NHEADS * S_LEN * 64]; // Q split (row: 32 hi|32 mid)
__device__ uint32_t g_Ks[BATCH * NHEADS * S_LEN * 64]; // K split
__device__ float    g_V [BATCH * NHEADS * S_LEN * DK]; // V fp32 (b,h,s,d)
__device__ uint32_t g_Vts[BATCH * NHEADS * DK * (S_LEN / 2) * 2]; // V^T split (b,h,d,s)
__device__ uint32_t g_Os[MROWS * DMODEL];              // attention out, split

// ===========================================================================
// PTX helpers
// ===========================================================================
__device__ __forceinline__ uint32_t smem_u32(const void* p) {
    uint32_t a;
    asm("{ .reg .u64 t; cvta.to.shared.u64 t, %1; cvt.u32.u64 %0, t; }"
        : "=r"(a) : "l"(p));
    return a;
}
__device__ __forceinline__ void cp_async16(uint32_t dst, const void* src) {
    asm volatile("cp.async.cg.shared.global [%0], [%1], 16;"
                 :: "r"(dst), "l"(src));
}
#define CP_COMMIT() asm volatile("cp.async.commit_group;" ::: "memory")
#define CP_WAIT1()  asm volatile("cp.async.wait_group 1;" ::: "memory")
#define CP_WAIT0()  asm volatile("cp.async.wait_group 0;" ::: "memory")

#define LDSM_X4(r0, r1, r2, r3, addr)                                     \
    asm volatile("ldmatrix.sync.aligned.m8n8.x4.shared.b16 "              \
                 "{%0,%1,%2,%3}, [%4];"                                   \
                 : "=r"(r0), "=r"(r1), "=r"(r2), "=r"(r3) : "r"(addr))

#define MMA_BF16(c, a, b0, b1)                                            \
    asm volatile("mma.sync.aligned.m16n8k16.row.col.f32.bf16.bf16.f32 "   \
                 "{%0,%1,%2,%3},{%4,%5,%6,%7},{%8,%9},{%0,%1,%2,%3};"     \
                 : "+f"((c)[0]), "+f"((c)[1]), "+f"((c)[2]), "+f"((c)[3]) \
                 : "r"((a)[0]), "r"((a)[1]), "r"((a)[2]), "r"((a)[3]),    \
                   "r"(b0), "r"(b1))

__device__ __forceinline__ void bf16_split2(float x0, float x1,
                                            uint32_t& hi2, uint32_t& mid2) {
    uint32_t h;
    asm("cvt.rn.bf16x2.f32 %0, %2, %1;" : "=r"(h) : "f"(x0), "f"(x1));
    float h0 = __uint_as_float(h << 16);
    float h1 = __uint_as_float(h & 0xffff0000u);
    float m0 = x0 - h0, m1 = x1 - h1;
    uint32_t m;
    asm("cvt.rn.bf16x2.f32 %0, %2, %1;" : "=r"(m) : "f"(m0), "f"(m1));
    hi2 = h; mid2 = m;
}

// ===========================================================================
// Fused split prep: x and the four weight matrices in one launch.
// rows 0..4095 -> x ; 4096+w*1024+wr -> W[w]
// ===========================================================================
__global__ __launch_bounds__(256) void split_all_kernel(
    const float* __restrict__ x,  const float* __restrict__ Wq,
    const float* __restrict__ Wk, const float* __restrict__ Wv,
    const float* __restrict__ Wo)
{
    int idx = blockIdx.x * 256 + threadIdx.x;   // one per 4-float group
    int r   = idx >> 8;
    int p4  = idx & 255;
    const float* src;
    uint32_t*    dstrow;
    if (r < MROWS) {
        src    = x    + ((size_t)r << 10);
        dstrow = g_Xs + ((size_t)r << 10);
    } else {
        int rr = r - MROWS;
        int w  = rr >> 10;
        int wr = rr & 1023;
        const float* ws = (w == 0) ? Wq : (w == 1) ? Wk : (w == 2) ? Wv : Wo;
        src    = ws + ((size_t)wr << 10);
        dstrow = g_Ws[w] + ((size_t)wr << 10);
    }
    int kb = p4 >> 3, q = p4 & 7;
    float4 v = *(const float4*)(src + p4 * 4);
    uint32_t h0, m0, h1, m1;
    bf16_split2(v.x, v.y, h0, m0);
    bf16_split2(v.z, v.w, h1, m1);
    uint32_t* o = dstrow + kb * 32;
    *(uint2*)(o + 2 * q)      = make_uint2(h0, h1);
    *(uint2*)(o + 16 + 2 * q) = make_uint2(m0, m1);
}

// ===========================================================================
// V transpose + split: g_V (b,h,s,d) f32 -> g_Vts (b,h,d,s) split
// ===========================================================================
__global__ __launch_bounds__(256) void vts_kernel() {
    __shared__ float sT[64 * 65];
    const int t  = threadIdx.x;
    const int s0 = blockIdx.x * 64;
    const int bh = blockIdx.y;
    const float* __restrict__ Vp = g_V + (size_t)bh * S_LEN * DK;

#pragma unroll
    for (int i = 0; i < 4; i++) {
        int idx = i * 256 + t, s = idx >> 4, ch = idx & 15;
        float4 v = *(const float4*)(Vp + (size_t)(s0 + s) * DK + ch * 4);
        sT[(ch * 4 + 0) * 65 + s] = v.x;
        sT[(ch * 4 + 1) * 65 + s] = v.y;
        sT[(ch * 4 + 2) * 65 + s] = v.z;
        sT[(ch * 4 + 3) * 65 + s] = v.w;
    }
    __syncthreads();

    const int d = t >> 2;
    const int q = t & 3;
    uint32_t* dst = g_Vts + (size_t)bh * 64 * 2048 + (size_t)d * 2048 +
                    ((s0 >> 5) + (q >> 1)) * 32;
    uint32_t hi[8], mid[8];
#pragma unroll
    for (int p = 0; p < 8; p++) {
        int sl = q * 16 + 2 * p;
        bf16_split2(sT[d * 65 + sl], sT[d * 65 + sl + 1], hi[p], mid[p]);
    }
    const int off = (q & 1) * 8;
#pragma unroll
    for (int p = 0; p < 8; p += 4) {
        *(uint4*)(dst + off + p)      = make_uint4(hi[p], hi[p+1], hi[p+2], hi[p+3]);
        *(uint4*)(dst + 16 + off + p) = make_uint4(mid[p], mid[p+1], mid[p+2], mid[p+3]);
    }
}

// ===========================================================================
// 3xBF16 GEMM, 3-stage cp.async ring (unchanged from R8).
// ===========================================================================
__global__ __launch_bounds__(256) void mma_gemm_kernel(
    const int* __restrict__ pos,
    float*     __restrict__ outp,
    int mode_sel)
{
    extern __shared__ char dynsmem[];

    const int mode = (mode_sel < 0) ? (int)blockIdx.z : mode_sel;
    const uint32_t* __restrict__ A = (mode == 3) ? g_Os : g_Xs;
    const uint32_t* __restrict__ W = g_Ws[mode];

    const int t   = threadIdx.x;
    const int wid = t >> 5;
    const int lid = t & 31;
    const int wm  = wid >> 2;
    const int wn  = wid & 3;
    const int n0  = blockIdx.x * 128;
    const int m0  = blockIdx.y * 128;

    uint32_t raw = smem_u32(dynsmem);
    uint32_t pad = (1024u - (raw & 1023u)) & 1023u;
    const uint32_t sbase = raw + pad;

    float c[4][4][4];
#pragma unroll
    for (int i = 0; i < 4; i++)
#pragma unroll
        for (int j = 0; j < 4; j++)
#pragma unroll
            for (int k = 0; k < 4; k++) c[i][j][k] = 0.f;

    auto stage_load = [&](int buf, int s) {
        const uint32_t sa = sbase + buf * 32768;
#pragma unroll
        for (int i = 0; i < 4; i++) {
            int idx = i * 256 + t;
            int row = idx >> 3;
            int ch  = idx & 7;
            uint32_t off = (uint32_t)(row * 128 + ((ch ^ (row & 7)) << 4));
            cp_async16(sa + off,         A + (size_t)(m0 + row) * 1024 + s * 32 + ch * 4);
            cp_async16(sa + 16384 + off, W + (size_t)(n0 + row) * 1024 + s * 32 + ch * 4);
        }
        CP_COMMIT();
    };

    stage_load(0, 0);
    stage_load(1, 1);

    int buf = 0;
    for (int s = 0; s < 32; s++) {
        if (s == 31) { CP_WAIT0(); } else { CP_WAIT1(); }
        __syncthreads();
        if (s + 2 < 32) {
            int nb = buf + 2; if (nb >= 3) nb -= 3;
            stage_load(nb, s + 2);
        }

        const uint32_t As_a = sbase + buf * 32768;
        const uint32_t Bs_a = As_a + 16384;

#pragma unroll
        for (int kc = 0; kc < 2; kc++) {
            uint32_t bhf[2][4], bmf[2][4];
#pragma unroll
            for (int ng = 0; ng < 2; ng++) {
                int row = wn * 32 + ng * 16 + ((lid >> 4) << 3) + (lid & 7);
                int ch  = 2 * kc + ((lid >> 3) & 1);
                uint32_t rb = Bs_a + row * 128;
                LDSM_X4(bhf[ng][0], bhf[ng][1], bhf[ng][2], bhf[ng][3],
                        rb + ((ch ^ (row & 7)) << 4));
                LDSM_X4(bmf[ng][0], bmf[ng][1], bmf[ng][2], bmf[ng][3],
                        rb + (((ch + 4) ^ (row & 7)) << 4));
            }
#pragma unroll
            for (int mi = 0; mi < 4; mi++) {
                int row = wm * 64 + mi * 16 + (lid & 15);
                int ch  = 2 * kc + (lid >> 4);
                uint32_t ra = As_a + row * 128;
                uint32_t ah[4], am[4];
                LDSM_X4(ah[0], ah[1], ah[2], ah[3], ra + ((ch ^ (row & 7)) << 4));
                LDSM_X4(am[0], am[1], am[2], am[3], ra + (((ch + 4) ^ (row & 7)) << 4));
#pragma unroll
                for (int ng = 0; ng < 2; ng++) {
                    MMA_BF16(c[mi][2 * ng],     am, bhf[ng][0], bhf[ng][1]);
                    MMA_BF16(c[mi][2 * ng],     ah, bmf[ng][0], bmf[ng][1]);
                    MMA_BF16(c[mi][2 * ng],     ah, bhf[ng][0], bhf[ng][1]);
                    MMA_BF16(c[mi][2 * ng + 1], am, bhf[ng][2], bhf[ng][3]);
                    MMA_BF16(c[mi][2 * ng + 1], ah, bmf[ng][2], bmf[ng][3]);
                    MMA_BF16(c[mi][2 * ng + 1], ah, bhf[ng][2], bhf[ng][3]);
                }
            }
        }
        buf++; if (buf >= 3) buf -= 3;
    }

    // ---------------- epilogue ----------------
    const int rbase = m0 + wm * 64 + (lid >> 2);
    const int cbase = n0 + wn * 32 + (lid & 3) * 2;
    const float neg_lt = -logf(10000.0f) / 64.0f;

    if (mode == 3) {
#pragma unroll
        for (int mi = 0; mi < 4; mi++) {
#pragma unroll
            for (int nj = 0; nj < 4; nj++) {
                int row0 = rbase + mi * 16;
                int col  = cbase + nj * 8;
                *(float2*)(outp + (size_t)row0 * DMODEL + col) =
                    make_float2(c[mi][nj][0], c[mi][nj][1]);
                *(float2*)(outp + (size_t)(row0 + 8) * DMODEL + col) =
                    make_float2(c[mi][nj][2], c[mi][nj][3]);
            }
        }
    } else if (mode == 2) {
#pragma unroll
        for (int mi = 0; mi < 4; mi++) {
#pragma unroll
            for (int half = 0; half < 2; half++) {
                int row  = rbase + mi * 16 + half * 8;
                int b    = row >> 11;
                int srow = row & (S_LEN - 1);
#pragma unroll
                for (int nj = 0; nj < 4; nj++) {
                    int col = cbase + nj * 8;
                    int h   = col >> 6;
                    int d   = col & 63;
                    *(float2*)(g_V + (((size_t)(b * NHEADS + h) * S_LEN + srow) * DK) + d) =
                        make_float2(c[mi][nj][half * 2], c[mi][nj][half * 2 + 1]);
                }
            }
        }
    } else {
        uint32_t* basep = (mode == 0) ? g_Qs : g_Ks;
        const float osc = (mode == 0) ? QSCALE : 1.0f;
#pragma unroll
        for (int mi = 0; mi < 4; mi++) {
#pragma unroll
            for (int half = 0; half < 2; half++) {
                int row  = rbase + mi * 16 + half * 8;
                int b    = row >> 11;
                int srow = row & (S_LEN - 1);
                float p  = (float)pos[srow];
#pragma unroll
                for (int nj = 0; nj < 4; nj++) {
                    int col = cbase + nj * 8;
                    int h   = col >> 6;
                    int d   = col & 63;
                    float x1 = c[mi][nj][half * 2];
                    float x2 = c[mi][nj][half * 2 + 1];
                    float fr = expf((float)d * neg_lt);
                    float sn, cs;
                    sincosf(p * fr, &sn, &cs);
                    float r1 = (x1 * cs - x2 * sn) * osc;
                    float r2 = (x1 * sn + x2 * cs) * osc;
                    uint32_t hi, mid;
                    bf16_split2(r1, r2, hi, mid);
                    uint32_t* dst = basep +
                        ((size_t)(b * NHEADS + h) * S_LEN + srow) * 64;
                    dst[d >> 1]        = hi;
                    dst[32 + (d >> 1)] = mid;
                }
            }
        }
    }
}

// ===========================================================================
// 3xBF16 flash attention (causal). CTA: 128 q-rows of one (b,h); 8 warps.
// K and V both cp.async double-buffered; P converted to A-fragments in
// registers (no smem round trip). Smem 96KB -> 2 CTAs/SM.
// ===========================================================================
__global__ __launch_bounds__(256, 2) void attn_mma_kernel()
{
    extern __shared__ char dynsmem[];

    const int t   = threadIdx.x;
    const int wid = t >> 5;
    const int lid = t & 31;
    const int q0  = blockIdx.x * 128;
    const int bh  = blockIdx.y;
    const int b   = bh >> 4;
    const int h   = bh & 15;

    const uint32_t* __restrict__ Qg  = g_Qs  + (size_t)bh * S_LEN * 64;
    const uint32_t* __restrict__ Kg  = g_Ks  + (size_t)bh * S_LEN * 64;
    const uint32_t* __restrict__ Vtg = g_Vts + (size_t)bh * 64 * 2048;

    uint32_t raw = smem_u32(dynsmem);
    uint32_t pad = (1024u - (raw & 1023u)) & 1023u;
    const uint32_t sQ = raw + pad;
    const uint32_t sKb[2] = {sQ + 32768, sQ + 49152};
    const uint32_t sVb[2] = {sQ + 65536, sQ + 81920};

    auto load_k = [&](uint32_t sdst, int kv0) {
#pragma unroll
        for (int i = 0; i < 4; i++) {
            int idx = i * 256 + t, row = idx >> 4, ch = idx & 15;
            cp_async16(sdst + row * 256 + (ch & 8) * 16 +
                           (((ch & 7) ^ (row & 7)) << 4),
                       Kg + (size_t)(kv0 + row) * 64 + ch * 4);
        }
    };
    // g_Vts tile: per d-row, 64 contiguous u32 = [hi0 mid0 hi1 mid1] 16B-chunk
    // groups; remap to smem layout [hi0 hi1 | mid0 mid1] with swizzle.
    auto load_v = [&](uint32_t sdst, int kv0) {
#pragma unroll
        for (int i = 0; i < 4; i++) {
            int idx = i * 256 + t, d = idx >> 4, ch = idx & 15;
            int g = ch >> 2, bq = ch & 3;
            int chd = (((g << 1) | (g >> 1)) & 3) * 4 + bq;
            cp_async16(sdst + d * 256 + (chd & 8) * 16 +
                           (((chd & 7) ^ (d & 7)) << 4),
                       Vtg + (size_t)d * 2048 + kv0 + ch * 4);
        }
    };

    // prologue: Q + tile0 (group 0), tile1 (group 1)
#pragma unroll
    for (int i = 0; i < 8; i++) {
        int idx = i * 256 + t, row = idx >> 4, ch = idx & 15;
        cp_async16(sQ + row * 256 + (ch & 8) * 16 +
                       (((ch & 7) ^ (row & 7)) << 4),
                   Qg + (size_t)(q0 + row) * 64 + ch * 4);
    }
    load_k(sKb[0], 0);
    load_v(sVb[0], 0);
    CP_COMMIT();
    const int ntiles = (q0 >> 6) + 2;   // always >= 2
    load_k(sKb[1], 64);
    load_v(sVb[1], 64);
    CP_COMMIT();
    CP_WAIT1();
    __syncthreads();

    float o[8][4];
#pragma unroll
    for (int i = 0; i < 8; i++)
#pragma unroll
        for (int j = 0; j < 4; j++) o[i][j] = 0.f;
    float mrow[2] = {-1e30f, -1e30f};
    float lrow[2] = {0.f, 0.f};

    const int wq_min = q0 + 16 * wid;
    const int wq_max = wq_min + 15;

    for (int kt = 0; kt < ntiles; kt++) {
        const int k0 = kt * 64;
        const uint32_t sKc = sKb[kt & 1];
        const uint32_t sVc = sVb[kt & 1];

        if (k0 <= wq_max) {
            // ---- S = Q K^T (3xBF16), Q pre-scaled by 0.125*log2e ----
            float s[8][4];
#pragma unroll
            for (int i = 0; i < 8; i++)
#pragma unroll
                for (int j = 0; j < 4; j++) s[i][j] = 0.f;

#pragma unroll
            for (int kc = 0; kc < 4; kc++) {
                int rowa = 16 * wid + (lid & 15);
                int cha  = 2 * kc + (lid >> 4);
                uint32_t ra = sQ + rowa * 256;
                uint32_t ah[4], am[4];
                LDSM_X4(ah[0], ah[1], ah[2], ah[3],
                        ra + ((cha ^ (rowa & 7)) << 4));
                LDSM_X4(am[0], am[1], am[2], am[3],
                        ra + 128 + ((cha ^ (rowa & 7)) << 4));
#pragma unroll
                for (int ng = 0; ng < 4; ng++) {
                    int rowb = ng * 16 + ((lid >> 4) << 3) + (lid & 7);
                    int chb  = 2 * kc + ((lid >> 3) & 1);
                    uint32_t rb = sKc + rowb * 256;
                    uint32_t bhf[4], bmf[4];
                    LDSM_X4(bhf[0], bhf[1], bhf[2], bhf[3],
                            rb + ((chb ^ (rowb & 7)) << 4));
                    LDSM_X4(bmf[0], bmf[1], bmf[2], bmf[3],
                            rb + 128 + ((chb ^ (rowb & 7)) << 4));
                    MMA_BF16(s[2 * ng],     am, bhf[0], bhf[1]);
                    MMA_BF16(s[2 * ng],     ah, bmf[0], bmf[1]);
                    MMA_BF16(s[2 * ng],     ah, bhf[0], bhf[1]);
                    MMA_BF16(s[2 * ng + 1], am, bhf[2], bhf[3]);
                    MMA_BF16(s[2 * ng + 1], ah, bmf[2], bmf[3]);
                    MMA_BF16(s[2 * ng + 1], ah, bhf[2], bhf[3]);
                }
            }

            // ---- causal mask (whenever tile passes warp's first q row) ----
            const int qA = q0 + 16 * wid + (lid >> 2);
            if (k0 + 63 > wq_min) {
#pragma unroll
                for (int nf = 0; nf < 8; nf++) {
                    int colb = k0 + nf * 8 + 2 * (lid & 3);
#pragma unroll
                    for (int e = 0; e < 4; e++) {
                        int q  = qA + ((e >> 1) << 3);
                        int kv = colb + (e & 1);
                        if (kv > q) s[nf][e] = -1e30f;
                    }
                }
            }

            // ---- online softmax (log2 domain) ----
#pragma unroll
            for (int half = 0; half < 2; half++) {
                float ml = -1e30f;
#pragma unroll
                for (int nf = 0; nf < 8; nf++)
                    ml = fmaxf(ml, fmaxf(s[nf][2 * half], s[nf][2 * half + 1]));
                ml = fmaxf(ml, __shfl_xor_sync(0xffffffffu, ml, 1));
                ml = fmaxf(ml, __shfl_xor_sync(0xffffffffu, ml, 2));
                float mn = fmaxf(mrow[half], ml);
                float al = exp2f(mrow[half] - mn);
                mrow[half] = mn;
                float ls = 0.f;
#pragma unroll
                for (int nf = 0; nf < 8; nf++) {
                    float e0 = exp2f(s[nf][2 * half] - mn);
                    float e1 = exp2f(s[nf][2 * half + 1] - mn);
                    s[nf][2 * half] = e0;
                    s[nf][2 * half + 1] = e1;
                    ls += e0 + e1;
                }
                ls += __shfl_xor_sync(0xffffffffu, ls, 1);
                ls += __shfl_xor_sync(0xffffffffu, ls, 2);
                lrow[half] = lrow[half] * al + ls;
#pragma unroll
                for (int nf = 0; nf < 8; nf++) {
                    o[nf][2 * half] *= al;
                    o[nf][2 * half + 1] *= al;
                }
            }

            // ---- O += P V : P converted to A-fragments in registers ----
#pragma unroll
            for (int kc = 0; kc < 4; kc++) {
                uint32_t ph[4], pm[4];
                bf16_split2(s[2 * kc][0],     s[2 * kc][1],     ph[0], pm[0]);
                bf16_split2(s[2 * kc][2],     s[2 * kc][3],     ph[1], pm[1]);
                bf16_split2(s[2 * kc + 1][0], s[2 * kc + 1][1], ph[2], pm[2]);
                bf16_split2(s[2 * kc + 1][2], s[2 * kc + 1][3], ph[3], pm[3]);
#pragma unroll
                for (int ng = 0; ng < 4; ng++) {
                    int rowb = ng * 16 + ((lid >> 4) << 3) + (lid & 7);
                    int chb  = 2 * kc + ((lid >> 3) & 1);
                    uint32_t rb = sVc + rowb * 256;
                    uint32_t vh[4], vm[4];
                    LDSM_X4(vh[0], vh[1], vh[2], vh[3],
                            rb + ((chb ^ (rowb & 7)) << 4));
                    LDSM_X4(vm[0], vm[1], vm[2], vm[3],
                            rb + 128 + ((chb ^ (rowb & 7)) << 4));
                    MMA_BF16(o[2 * ng],     pm, vh[0], vh[1]);
                    MMA_BF16(o[2 * ng],     ph, vm[0], vm[1]);
                    MMA_BF16(o[2 * ng],     ph, vh[0], vh[1]);
                    MMA_BF16(o[2 * ng + 1], pm, vh[2], vh[3]);
                    MMA_BF16(o[2 * ng + 1], ph, vm[2], vm[3]);
                    MMA_BF16(o[2 * ng + 1], ph, vh[2], vh[3]);
                }
            }
        }

        __syncthreads();   // all warps done with buffers of tile kt
        bool more = (kt + 2 < ntiles);
        if (more) {
            load_k(sKb[kt & 1], (kt + 2) * 64);
            load_v(sVb[kt & 1], (kt + 2) * 64);
            CP_COMMIT();
        }
        if (kt + 1 < ntiles) {
            if (more) { CP_WAIT1(); } else { CP_WAIT0(); }
            __syncthreads();
        }
    }

    // ---- normalize + write split rows into g_Os ----
    const float i0 = 1.0f / lrow[0];
    const float i1 = 1.0f / lrow[1];
    const int qA = q0 + 16 * wid + (lid >> 2);
    const size_t row0 = (size_t)(b * S_LEN + qA) * 1024;
    const size_t row1 = (size_t)(b * S_LEN + qA + 8) * 1024;
#pragma unroll
    for (int nf = 0; nf < 8; nf++) {
        int col = h * 64 + nf * 8 + 2 * (lid & 3);
        int kb = col >> 5;
        int jj = (col & 31) >> 1;
        uint32_t hi, mid;
        bf16_split2(o[nf][0] * i0, o[nf][1] * i0, hi, mid);
        g_Os[row0 + kb * 32 + jj]      = hi;
        g_Os[row0 + kb * 32 + 16 + jj] = mid;
        bf16_split2(o[nf][2] * i1, o[nf][3] * i1, hi, mid);
        g_Os[row1 + kb * 32 + jj]      = hi;
        g_Os[row1 + kb * 32 + 16 + jj] = mid;
    }
}

// ---------------------------------------------------------------------------
extern "C" void kernel_launch(void* const* d_in, const int* in_sizes, int n_in,
                              void* d_out, int out_size)
{
    const float* x   = (const float*)d_in[0];
    const int*   pos = (const int*)  d_in[1];
    const float* Wq  = (const float*)d_in[2];
    const float* Wk  = (const float*)d_in[3];
    const float* Wv  = (const float*)d_in[4];
    const float* Wo  = (const float*)d_in[5];
    float* out = (float*)d_out;

    const int DYN_GEMM = 3 * 32768 + 1024;
    const int DYN_ATTN = 98304 + 1024;
    cudaFuncSetAttribute(mma_gemm_kernel,
                         cudaFuncAttributeMaxDynamicSharedMemorySize, DYN_GEMM);
    cudaFuncSetAttribute(attn_mma_kernel,
                         cudaFuncAttributeMaxDynamicSharedMemorySize, DYN_ATTN);

    // Fused split prep (x + 4 weights)
    split_all_kernel<<<MROWS + 4 * DMODEL, 256>>>(x, Wq, Wk, Wv, Wo);

    // QKV projections + RoPE (3xBF16)
    mma_gemm_kernel<<<dim3(DMODEL / 128, MROWS / 128, 3), 256, DYN_GEMM>>>(
        pos, nullptr, -1);
    // V transpose + split for attention
    vts_kernel<<<dim3(S_LEN / 64, BATCH * NHEADS), 256>>>();
    // Causal flash attention (3xBF16)
    attn_mma_kernel<<<dim3(S_LEN / 128, BATCH * NHEADS), 256, DYN_ATTN>>>();
    // Output projection (3xBF16)
    mma_gemm_kernel<<<dim3(DMODEL / 128, MROWS / 128, 1), 256, DYN_GEMM>>>(
        pos, out, 3);
}

// round 15
// speedup vs baseline: 4.2778x; 1.1486x over previous
#include <cuda_runtime.h>
#include <cuda_bf16.h>
#include <math.h>
#include <stdint.h>

#define S_LEN  2048
#define DMODEL 1024
#define NHEADS 16
#define DK     64
#define BATCH  2
#define MROWS  (BATCH * S_LEN)   // 4096

// qk scale 1/8 folded with log2(e) into Q, so softmax uses exp2
#define QSCALE 0.18033688011112042f   // 0.125 * log2(e)

// ---------------------------------------------------------------------------
// Device-global scratch. Split layout per 32-col block: [16 u32 hi | 16 u32 mid]
// (bf16x2 per u32, pair = adjacent columns)
// ---------------------------------------------------------------------------
__device__ uint32_t g_Xs[MROWS * DMODEL];              // x split
__device__ uint32_t g_Ws[4][DMODEL * DMODEL];          // Wq,Wk,Wv,Wo split
__device__ uint32_t g_Qs[BATCH * NHEADS * S_LEN * 64]; // Q split (row: 32 hi|32 mid)
__device__ uint32_t g_Ks[BATCH * NHEADS * S_LEN * 64]; // K split
__device__ float    g_V [BATCH * NHEADS * S_LEN * DK]; // V fp32 (b,h,s,d)
__device__ uint32_t g_Vts[BATCH * NHEADS * DK * (S_LEN / 2) * 2]; // V^T split (b,h,d,s)
__device__ uint32_t g_Os[MROWS * DMODEL];              // attention out, split

// ===========================================================================
// PTX helpers
// ===========================================================================
__device__ __forceinline__ uint32_t smem_u32(const void* p) {
    uint32_t a;
    asm("{ .reg .u64 t; cvta.to.shared.u64 t, %1; cvt.u32.u64 %0, t; }"
        : "=r"(a) : "l"(p));
    return a;
}
__device__ __forceinline__ void cp_async16(uint32_t dst, const void* src) {
    asm volatile("cp.async.cg.shared.global [%0], [%1], 16;"
                 :: "r"(dst), "l"(src));
}
#define CP_COMMIT() asm volatile("cp.async.commit_group;" ::: "memory")
#define CP_WAIT1()  asm volatile("cp.async.wait_group 1;" ::: "memory")
#define CP_WAIT0()  asm volatile("cp.async.wait_group 0;" ::: "memory")

#define LDSM_X4(r0, r1, r2, r3, addr)                                     \
    asm volatile("ldmatrix.sync.aligned.m8n8.x4.shared.b16 "              \
                 "{%0,%1,%2,%3}, [%4];"                                   \
                 : "=r"(r0), "=r"(r1), "=r"(r2), "=r"(r3) : "r"(addr))

#define MMA_BF16(c, a, b0, b1)                                            \
    asm volatile("mma.sync.aligned.m16n8k16.row.col.f32.bf16.bf16.f32 "   \
                 "{%0,%1,%2,%3},{%4,%5,%6,%7},{%8,%9},{%0,%1,%2,%3};"     \
                 : "+f"((c)[0]), "+f"((c)[1]), "+f"((c)[2]), "+f"((c)[3]) \
                 : "r"((a)[0]), "r"((a)[1]), "r"((a)[2]), "r"((a)[3]),    \
                   "r"(b0), "r"(b1))

__device__ __forceinline__ void bf16_split2(float x0, float x1,
                                            uint32_t& hi2, uint32_t& mid2) {
    uint32_t h;
    asm("cvt.rn.bf16x2.f32 %0, %2, %1;" : "=r"(h) : "f"(x0), "f"(x1));
    float h0 = __uint_as_float(h << 16);
    float h1 = __uint_as_float(h & 0xffff0000u);
    float m0 = x0 - h0, m1 = x1 - h1;
    uint32_t m;
    asm("cvt.rn.bf16x2.f32 %0, %2, %1;" : "=r"(m) : "f"(m0), "f"(m1));
    hi2 = h; mid2 = m;
}

// ===========================================================================
// Fused split prep: x and the four weight matrices in one launch.
// ===========================================================================
__global__ __launch_bounds__(256) void split_all_kernel(
    const float* __restrict__ x,  const float* __restrict__ Wq,
    const float* __restrict__ Wk, const float* __restrict__ Wv,
    const float* __restrict__ Wo)
{
    int idx = blockIdx.x * 256 + threadIdx.x;   // one per 4-float group
    int r   = idx >> 8;
    int p4  = idx & 255;
    const float* src;
    uint32_t*    dstrow;
    if (r < MROWS) {
        src    = x    + ((size_t)r << 10);
        dstrow = g_Xs + ((size_t)r << 10);
    } else {
        int rr = r - MROWS;
        int w  = rr >> 10;
        int wr = rr & 1023;
        const float* ws = (w == 0) ? Wq : (w == 1) ? Wk : (w == 2) ? Wv : Wo;
        src    = ws + ((size_t)wr << 10);
        dstrow = g_Ws[w] + ((size_t)wr << 10);
    }
    int kb = p4 >> 3, q = p4 & 7;
    float4 v = *(const float4*)(src + p4 * 4);
    uint32_t h0, m0, h1, m1;
    bf16_split2(v.x, v.y, h0, m0);
    bf16_split2(v.z, v.w, h1, m1);
    uint32_t* o = dstrow + kb * 32;
    *(uint2*)(o + 2 * q)      = make_uint2(h0, h1);
    *(uint2*)(o + 16 + 2 * q) = make_uint2(m0, m1);
}

// ===========================================================================
// V transpose + split: g_V (b,h,s,d) f32 -> g_Vts (b,h,d,s) split
// ===========================================================================
__global__ __launch_bounds__(256) void vts_kernel() {
    __shared__ float sT[64 * 65];
    const int t  = threadIdx.x;
    const int s0 = blockIdx.x * 64;
    const int bh = blockIdx.y;
    const float* __restrict__ Vp = g_V + (size_t)bh * S_LEN * DK;

#pragma unroll
    for (int i = 0; i < 4; i++) {
        int idx = i * 256 + t, s = idx >> 4, ch = idx & 15;
        float4 v = *(const float4*)(Vp + (size_t)(s0 + s) * DK + ch * 4);
        sT[(ch * 4 + 0) * 65 + s] = v.x;
        sT[(ch * 4 + 1) * 65 + s] = v.y;
        sT[(ch * 4 + 2) * 65 + s] = v.z;
        sT[(ch * 4 + 3) * 65 + s] = v.w;
    }
    __syncthreads();

    const int d = t >> 2;
    const int q = t & 3;
    uint32_t* dst = g_Vts + (size_t)bh * 64 * 2048 + (size_t)d * 2048 +
                    ((s0 >> 5) + (q >> 1)) * 32;
    uint32_t hi[8], mid[8];
#pragma unroll
    for (int p = 0; p < 8; p++) {
        int sl = q * 16 + 2 * p;
        bf16_split2(sT[d * 65 + sl], sT[d * 65 + sl + 1], hi[p], mid[p]);
    }
    const int off = (q & 1) * 8;
#pragma unroll
    for (int p = 0; p < 8; p += 4) {
        *(uint4*)(dst + off + p)      = make_uint4(hi[p], hi[p+1], hi[p+2], hi[p+3]);
        *(uint4*)(dst + 16 + off + p) = make_uint4(mid[p], mid[p+1], mid[p+2], mid[p+3]);
    }
}

// ===========================================================================
// 3xBF16 GEMM, 3-stage cp.async ring.
// ===========================================================================
__global__ __launch_bounds__(256) void mma_gemm_kernel(
    const int* __restrict__ pos,
    float*     __restrict__ outp,
    int mode_sel)
{
    extern __shared__ char dynsmem[];

    const int mode = (mode_sel < 0) ? (int)blockIdx.z : mode_sel;
    const uint32_t* __restrict__ A = (mode == 3) ? g_Os : g_Xs;
    const uint32_t* __restrict__ W = g_Ws[mode];

    const int t   = threadIdx.x;
    const int wid = t >> 5;
    const int lid = t & 31;
    const int wm  = wid >> 2;
    const int wn  = wid & 3;
    const int n0  = blockIdx.x * 128;
    const int m0  = blockIdx.y * 128;

    uint32_t raw = smem_u32(dynsmem);
    uint32_t pad = (1024u - (raw & 1023u)) & 1023u;
    const uint32_t sbase = raw + pad;

    float c[4][4][4];
#pragma unroll
    for (int i = 0; i < 4; i++)
#pragma unroll
        for (int j = 0; j < 4; j++)
#pragma unroll
            for (int k = 0; k < 4; k++) c[i][j][k] = 0.f;

    auto stage_load = [&](int buf, int s) {
        const uint32_t sa = sbase + buf * 32768;
#pragma unroll
        for (int i = 0; i < 4; i++) {
            int idx = i * 256 + t;
            int row = idx >> 3;
            int ch  = idx & 7;
            uint32_t off = (uint32_t)(row * 128 + ((ch ^ (row & 7)) << 4));
            cp_async16(sa + off,         A + (size_t)(m0 + row) * 1024 + s * 32 + ch * 4);
            cp_async16(sa + 16384 + off, W + (size_t)(n0 + row) * 1024 + s * 32 + ch * 4);
        }
        CP_COMMIT();
    };

    stage_load(0, 0);
    stage_load(1, 1);

    int buf = 0;
    for (int s = 0; s < 32; s++) {
        if (s == 31) { CP_WAIT0(); } else { CP_WAIT1(); }
        __syncthreads();
        if (s + 2 < 32) {
            int nb = buf + 2; if (nb >= 3) nb -= 3;
            stage_load(nb, s + 2);
        }

        const uint32_t As_a = sbase + buf * 32768;
        const uint32_t Bs_a = As_a + 16384;

#pragma unroll
        for (int kc = 0; kc < 2; kc++) {
            uint32_t bhf[2][4], bmf[2][4];
#pragma unroll
            for (int ng = 0; ng < 2; ng++) {
                int row = wn * 32 + ng * 16 + ((lid >> 4) << 3) + (lid & 7);
                int ch  = 2 * kc + ((lid >> 3) & 1);
                uint32_t rb = Bs_a + row * 128;
                LDSM_X4(bhf[ng][0], bhf[ng][1], bhf[ng][2], bhf[ng][3],
                        rb + ((ch ^ (row & 7)) << 4));
                LDSM_X4(bmf[ng][0], bmf[ng][1], bmf[ng][2], bmf[ng][3],
                        rb + (((ch + 4) ^ (row & 7)) << 4));
            }
#pragma unroll
            for (int mi = 0; mi < 4; mi++) {
                int row = wm * 64 + mi * 16 + (lid & 15);
                int ch  = 2 * kc + (lid >> 4);
                uint32_t ra = As_a + row * 128;
                uint32_t ah[4], am[4];
                LDSM_X4(ah[0], ah[1], ah[2], ah[3], ra + ((ch ^ (row & 7)) << 4));
                LDSM_X4(am[0], am[1], am[2], am[3], ra + (((ch + 4) ^ (row & 7)) << 4));
#pragma unroll
                for (int ng = 0; ng < 2; ng++) {
                    MMA_BF16(c[mi][2 * ng],     am, bhf[ng][0], bhf[ng][1]);
                    MMA_BF16(c[mi][2 * ng],     ah, bmf[ng][0], bmf[ng][1]);
                    MMA_BF16(c[mi][2 * ng],     ah, bhf[ng][0], bhf[ng][1]);
                    MMA_BF16(c[mi][2 * ng + 1], am, bhf[ng][2], bhf[ng][3]);
                    MMA_BF16(c[mi][2 * ng + 1], ah, bmf[ng][2], bmf[ng][3]);
                    MMA_BF16(c[mi][2 * ng + 1], ah, bhf[ng][2], bhf[ng][3]);
                }
            }
        }
        buf++; if (buf >= 3) buf -= 3;
    }

    // ---------------- epilogue ----------------
    const int rbase = m0 + wm * 64 + (lid >> 2);
    const int cbase = n0 + wn * 32 + (lid & 3) * 2;
    const float neg_lt = -logf(10000.0f) / 64.0f;

    if (mode == 3) {
#pragma unroll
        for (int mi = 0; mi < 4; mi++) {
#pragma unroll
            for (int nj = 0; nj < 4; nj++) {
                int row0 = rbase + mi * 16;
                int col  = cbase + nj * 8;
                *(float2*)(outp + (size_t)row0 * DMODEL + col) =
                    make_float2(c[mi][nj][0], c[mi][nj][1]);
                *(float2*)(outp + (size_t)(row0 + 8) * DMODEL + col) =
                    make_float2(c[mi][nj][2], c[mi][nj][3]);
            }
        }
    } else if (mode == 2) {
#pragma unroll
        for (int mi = 0; mi < 4; mi++) {
#pragma unroll
            for (int half = 0; half < 2; half++) {
                int row  = rbase + mi * 16 + half * 8;
                int b    = row >> 11;
                int srow = row & (S_LEN - 1);
#pragma unroll
                for (int nj = 0; nj < 4; nj++) {
                    int col = cbase + nj * 8;
                    int h   = col >> 6;
                    int d   = col & 63;
                    *(float2*)(g_V + (((size_t)(b * NHEADS + h) * S_LEN + srow) * DK) + d) =
                        make_float2(c[mi][nj][half * 2], c[mi][nj][half * 2 + 1]);
                }
            }
        }
    } else {
        uint32_t* basep = (mode == 0) ? g_Qs : g_Ks;
        const float osc = (mode == 0) ? QSCALE : 1.0f;
#pragma unroll
        for (int mi = 0; mi < 4; mi++) {
#pragma unroll
            for (int half = 0; half < 2; half++) {
                int row  = rbase + mi * 16 + half * 8;
                int b    = row >> 11;
                int srow = row & (S_LEN - 1);
                float p  = (float)pos[srow];
#pragma unroll
                for (int nj = 0; nj < 4; nj++) {
                    int col = cbase + nj * 8;
                    int h   = col >> 6;
                    int d   = col & 63;
                    float x1 = c[mi][nj][half * 2];
                    float x2 = c[mi][nj][half * 2 + 1];
                    float fr = expf((float)d * neg_lt);
                    float sn, cs;
                    sincosf(p * fr, &sn, &cs);
                    float r1 = (x1 * cs - x2 * sn) * osc;
                    float r2 = (x1 * sn + x2 * cs) * osc;
                    uint32_t hi, mid;
                    bf16_split2(r1, r2, hi, mid);
                    uint32_t* dst = basep +
                        ((size_t)(b * NHEADS + h) * S_LEN + srow) * 64;
                    dst[d >> 1]        = hi;
                    dst[32 + (d >> 1)] = mid;
                }
            }
        }
    }
}

// ===========================================================================
// 3xBF16 flash attention (causal). CTA: 128 q-rows of one (b,h); 8 warps.
// Grid: x = bh (32), y = q-tile issued LARGEST-FIRST (LPT scheduling).
// ===========================================================================
__global__ __launch_bounds__(256, 2) void attn_mma_kernel()
{
    extern __shared__ char dynsmem[];

    const int t   = threadIdx.x;
    const int wid = t >> 5;
    const int lid = t & 31;
    const int bh  = blockIdx.x;
    const int q0  = (int)(gridDim.y - 1 - blockIdx.y) * 128;  // big CTAs first
    const int b   = bh >> 4;
    const int h   = bh & 15;

    const uint32_t* __restrict__ Qg  = g_Qs  + (size_t)bh * S_LEN * 64;
    const uint32_t* __restrict__ Kg  = g_Ks  + (size_t)bh * S_LEN * 64;
    const uint32_t* __restrict__ Vtg = g_Vts + (size_t)bh * 64 * 2048;

    uint32_t raw = smem_u32(dynsmem);
    uint32_t pad = (1024u - (raw & 1023u)) & 1023u;
    const uint32_t sQ = raw + pad;
    const uint32_t sKb[2] = {sQ + 32768, sQ + 49152};
    const uint32_t sVb[2] = {sQ + 65536, sQ + 81920};

    auto load_k = [&](uint32_t sdst, int kv0) {
#pragma unroll
        for (int i = 0; i < 4; i++) {
            int idx = i * 256 + t, row = idx >> 4, ch = idx & 15;
            cp_async16(sdst + row * 256 + (ch & 8) * 16 +
                           (((ch & 7) ^ (row & 7)) << 4),
                       Kg + (size_t)(kv0 + row) * 64 + ch * 4);
        }
    };
    auto load_v = [&](uint32_t sdst, int kv0) {
#pragma unroll
        for (int i = 0; i < 4; i++) {
            int idx = i * 256 + t, d = idx >> 4, ch = idx & 15;
            int g = ch >> 2, bq = ch & 3;
            int chd = (((g << 1) | (g >> 1)) & 3) * 4 + bq;
            cp_async16(sdst + d * 256 + (chd & 8) * 16 +
                           (((chd & 7) ^ (d & 7)) << 4),
                       Vtg + (size_t)d * 2048 + kv0 + ch * 4);
        }
    };

    // prologue: Q + tile0 (group 0), tile1 (group 1)
#pragma unroll
    for (int i = 0; i < 8; i++) {
        int idx = i * 256 + t, row = idx >> 4, ch = idx & 15;
        cp_async16(sQ + row * 256 + (ch & 8) * 16 +
                       (((ch & 7) ^ (row & 7)) << 4),
                   Qg + (size_t)(q0 + row) * 64 + ch * 4);
    }
    load_k(sKb[0], 0);
    load_v(sVb[0], 0);
    CP_COMMIT();
    const int ntiles = (q0 >> 6) + 2;   // always >= 2
    load_k(sKb[1], 64);
    load_v(sVb[1], 64);
    CP_COMMIT();
    CP_WAIT1();
    __syncthreads();

    float o[8][4];
#pragma unroll
    for (int i = 0; i < 8; i++)
#pragma unroll
        for (int j = 0; j < 4; j++) o[i][j] = 0.f;
    float mrow[2] = {-1e30f, -1e30f};
    float lrow[2] = {0.f, 0.f};

    const int wq_min = q0 + 16 * wid;
    const int wq_max = wq_min + 15;

    for (int kt = 0; kt < ntiles; kt++) {
        const int k0 = kt * 64;
        const uint32_t sKc = sKb[kt & 1];
        const uint32_t sVc = sVb[kt & 1];

        if (k0 <= wq_max) {
            // ---- S = Q K^T (3xBF16), Q pre-scaled by 0.125*log2e ----
            float s[8][4];
#pragma unroll
            for (int i = 0; i < 8; i++)
#pragma unroll
                for (int j = 0; j < 4; j++) s[i][j] = 0.f;

#pragma unroll
            for (int kc = 0; kc < 4; kc++) {
                int rowa = 16 * wid + (lid & 15);
                int cha  = 2 * kc + (lid >> 4);
                uint32_t ra = sQ + rowa * 256;
                uint32_t ah[4], am[4];
                LDSM_X4(ah[0], ah[1], ah[2], ah[3],
                        ra + ((cha ^ (rowa & 7)) << 4));
                LDSM_X4(am[0], am[1], am[2], am[3],
                        ra + 128 + ((cha ^ (rowa & 7)) << 4));
#pragma unroll
                for (int ng = 0; ng < 4; ng++) {
                    int rowb = ng * 16 + ((lid >> 4) << 3) + (lid & 7);
                    int chb  = 2 * kc + ((lid >> 3) & 1);
                    uint32_t rb = sKc + rowb * 256;
                    uint32_t bhf[4], bmf[4];
                    LDSM_X4(bhf[0], bhf[1], bhf[2], bhf[3],
                            rb + ((chb ^ (rowb & 7)) << 4));
                    LDSM_X4(bmf[0], bmf[1], bmf[2], bmf[3],
                            rb + 128 + ((chb ^ (rowb & 7)) << 4));
                    MMA_BF16(s[2 * ng],     am, bhf[0], bhf[1]);
                    MMA_BF16(s[2 * ng],     ah, bmf[0], bmf[1]);
                    MMA_BF16(s[2 * ng],     ah, bhf[0], bhf[1]);
                    MMA_BF16(s[2 * ng + 1], am, bhf[2], bhf[3]);
                    MMA_BF16(s[2 * ng + 1], ah, bmf[2], bmf[3]);
                    MMA_BF16(s[2 * ng + 1], ah, bhf[2], bhf[3]);
                }
            }

            // ---- causal mask (whenever tile passes warp's first q row) ----
            const int qA = q0 + 16 * wid + (lid >> 2);
            if (k0 + 63 > wq_min) {
#pragma unroll
                for (int nf = 0; nf < 8; nf++) {
                    int colb = k0 + nf * 8 + 2 * (lid & 3);
#pragma unroll
                    for (int e = 0; e < 4; e++) {
                        int q  = qA + ((e >> 1) << 3);
                        int kv = colb + (e & 1);
                        if (kv > q) s[nf][e] = -1e30f;
                    }
                }
            }

            // ---- online softmax (log2 domain) ----
#pragma unroll
            for (int half = 0; half < 2; half++) {
                float ml = -1e30f;
#pragma unroll
                for (int nf = 0; nf < 8; nf++)
                    ml = fmaxf(ml, fmaxf(s[nf][2 * half], s[nf][2 * half + 1]));
                ml = fmaxf(ml, __shfl_xor_sync(0xffffffffu, ml, 1));
                ml = fmaxf(ml, __shfl_xor_sync(0xffffffffu, ml, 2));
                float mn = fmaxf(mrow[half], ml);
                float al = exp2f(mrow[half] - mn);
                mrow[half] = mn;
                float ls = 0.f;
#pragma unroll
                for (int nf = 0; nf < 8; nf++) {
                    float e0 = exp2f(s[nf][2 * half] - mn);
                    float e1 = exp2f(s[nf][2 * half + 1] - mn);
                    s[nf][2 * half] = e0;
                    s[nf][2 * half + 1] = e1;
                    ls += e0 + e1;
                }
                ls += __shfl_xor_sync(0xffffffffu, ls, 1);
                ls += __shfl_xor_sync(0xffffffffu, ls, 2);
                lrow[half] = lrow[half] * al + ls;
#pragma unroll
                for (int nf = 0; nf < 8; nf++) {
                    o[nf][2 * half] *= al;
                    o[nf][2 * half + 1] *= al;
                }
            }

            // ---- O += P V : P converted to A-fragments in registers ----
#pragma unroll
            for (int kc = 0; kc < 4; kc++) {
                uint32_t ph[4], pm[4];
                bf16_split2(s[2 * kc][0],     s[2 * kc][1],     ph[0], pm[0]);
                bf16_split2(s[2 * kc][2],     s[2 * kc][3],     ph[1], pm[1]);
                bf16_split2(s[2 * kc + 1][0], s[2 * kc + 1][1], ph[2], pm[2]);
                bf16_split2(s[2 * kc + 1][2], s[2 * kc + 1][3], ph[3], pm[3]);
#pragma unroll
                for (int ng = 0; ng < 4; ng++) {
                    int rowb = ng * 16 + ((lid >> 4) << 3) + (lid & 7);
                    int chb  = 2 * kc + ((lid >> 3) & 1);
                    uint32_t rb = sVc + rowb * 256;
                    uint32_t vh[4], vm[4];
                    LDSM_X4(vh[0], vh[1], vh[2], vh[3],
                            rb + ((chb ^ (rowb & 7)) << 4));
                    LDSM_X4(vm[0], vm[1], vm[2], vm[3],
                            rb + 128 + ((chb ^ (rowb & 7)) << 4));
                    MMA_BF16(o[2 * ng],     pm, vh[0], vh[1]);
                    MMA_BF16(o[2 * ng],     ph, vm[0], vm[1]);
                    MMA_BF16(o[2 * ng],     ph, vh[0], vh[1]);
                    MMA_BF16(o[2 * ng + 1], pm, vh[2], vh[3]);
                    MMA_BF16(o[2 * ng + 1], ph, vm[2], vm[3]);
                    MMA_BF16(o[2 * ng + 1], ph, vh[2], vh[3]);
                }
            }
        }

        __syncthreads();   // all warps done with buffers of tile kt
        bool more = (kt + 2 < ntiles);
        if (more) {
            load_k(sKb[kt & 1], (kt + 2) * 64);
            load_v(sVb[kt & 1], (kt + 2) * 64);
            CP_COMMIT();
        }
        if (kt + 1 < ntiles) {
            if (more) { CP_WAIT1(); } else { CP_WAIT0(); }
            __syncthreads();
        }
    }

    // ---- normalize + write split rows into g_Os ----
    const float i0 = 1.0f / lrow[0];
    const float i1 = 1.0f / lrow[1];
    const int qA = q0 + 16 * wid + (lid >> 2);
    const size_t row0 = (size_t)(b * S_LEN + qA) * 1024;
    const size_t row1 = (size_t)(b * S_LEN + qA + 8) * 1024;
#pragma unroll
    for (int nf = 0; nf < 8; nf++) {
        int col = h * 64 + nf * 8 + 2 * (lid & 3);
        int kb = col >> 5;
        int jj = (col & 31) >> 1;
        uint32_t hi, mid;
        bf16_split2(o[nf][0] * i0, o[nf][1] * i0, hi, mid);
        g_Os[row0 + kb * 32 + jj]      = hi;
        g_Os[row0 + kb * 32 + 16 + jj] = mid;
        bf16_split2(o[nf][2] * i1, o[nf][3] * i1, hi, mid);
        g_Os[row1 + kb * 32 + jj]      = hi;
        g_Os[row1 + kb * 32 + 16 + jj] = mid;
    }
}

// ---------------------------------------------------------------------------
extern "C" void kernel_launch(void* const* d_in, const int* in_sizes, int n_in,
                              void* d_out, int out_size)
{
    const float* x   = (const float*)d_in[0];
    const int*   pos = (const int*)  d_in[1];
    const float* Wq  = (const float*)d_in[2];
    const float* Wk  = (const float*)d_in[3];
    const float* Wv  = (const float*)d_in[4];
    const float* Wo  = (const float*)d_in[5];
    float* out = (float*)d_out;

    const int DYN_GEMM = 3 * 32768 + 1024;
    const int DYN_ATTN = 98304 + 1024;
    cudaFuncSetAttribute(mma_gemm_kernel,
                         cudaFuncAttributeMaxDynamicSharedMemorySize, DYN_GEMM);
    cudaFuncSetAttribute(attn_mma_kernel,
                         cudaFuncAttributeMaxDynamicSharedMemorySize, DYN_ATTN);

    // Fused split prep (x + 4 weights)
    split_all_kernel<<<MROWS + 4 * DMODEL, 256>>>(x, Wq, Wk, Wv, Wo);

    // QKV projections + RoPE (3xBF16)
    mma_gemm_kernel<<<dim3(DMODEL / 128, MROWS / 128, 3), 256, DYN_GEMM>>>(
        pos, nullptr, -1);
    // V transpose + split for attention
    vts_kernel<<<dim3(S_LEN / 64, BATCH * NHEADS), 256>>>();
    // Causal flash attention (3xBF16), LPT order: x = bh, y = q-tile (reversed)
    attn_mma_kernel<<<dim3(BATCH * NHEADS, S_LEN / 128), 256, DYN_ATTN>>>();
    // Output projection (3xBF16)
    mma_gemm_kernel<<<dim3(DMODEL / 128, MROWS / 128, 1), 256, DYN_GEMM>>>(
        pos, out, 3);
}